// round 10
// baseline (speedup 1.0000x reference)
#include <cuda_runtime.h>
#include <cuda_bf16.h>
#include <math.h>
#include <stdint.h>

// ---------------- problem constants ----------------
#define DIMX     512
#define INTER    64
#define NSH      2
#define NROUTED  64
#define NEXP     66
#define TOPK     6
#define KSLOT    8
#define NTOK     1024
#define NSLOT    (NTOK * KSLOT)
#define TILE_M   32
#define MAXTILES 384
#define ECAP     1024          // fixed per-expert segment capacity in g_perm

// ---------------- PTX helpers (sm_80-level only) ----------------
__device__ __forceinline__ uint32_t smem_u32(const void* p) {
    uint32_t a;
    asm("{ .reg .u64 t; cvta.to.shared.u64 t, %1; cvt.u32.u64 %0, t; }" : "=r"(a) : "l"(p));
    return a;
}
__device__ __forceinline__ void cp16(uint32_t sdst, const void* gsrc) {
    asm volatile("cp.async.cg.shared.global [%0], [%1], 16;" :: "r"(sdst), "l"(gsrc));
}
__device__ __forceinline__ void cp_commit() { asm volatile("cp.async.commit_group;"); }
template<int N> __device__ __forceinline__ void cp_wait() {
    asm volatile("cp.async.wait_group %0;" :: "n"(N));
}
__device__ __forceinline__ void ldsm4(uint32_t& r0, uint32_t& r1, uint32_t& r2, uint32_t& r3,
                                      uint32_t addr) {
    asm volatile("ldmatrix.sync.aligned.m8n8.x4.shared.b16 {%0,%1,%2,%3}, [%4];"
                 : "=r"(r0), "=r"(r1), "=r"(r2), "=r"(r3) : "r"(addr));
}
__device__ __forceinline__ void mma_bf16(float* c, const uint32_t* a, const uint32_t* b) {
    asm volatile(
        "mma.sync.aligned.m16n8k16.row.col.f32.bf16.bf16.f32 "
        "{%0,%1,%2,%3}, {%4,%5,%6,%7}, {%8,%9}, {%0,%1,%2,%3};"
        : "+f"(c[0]), "+f"(c[1]), "+f"(c[2]), "+f"(c[3])
        : "r"(a[0]), "r"(a[1]), "r"(a[2]), "r"(a[3]), "r"(b[0]), "r"(b[1]));
}

// ---------------- device scratch ----------------
__device__ int   g_eidx[NSLOT];
__device__ float g_wt[NSLOT];
__device__ int   g_pos[NSLOT];
__device__ int   g_counts[NEXP];
__device__ int   g_perm[NEXP * ECAP];
__device__ int4  g_tiles[MAXTILES];
__device__ int   g_ntiles;
__device__ float g_slot_out[(size_t)NSLOT * DIMX];

__device__ __nv_bfloat16 g_xhi[NTOK * DIMX];
__device__ __nv_bfloat16 g_xlo[NTOK * DIMX];
__device__ __nv_bfloat16 g_w13hi[(size_t)NEXP * 128 * DIMX];   // [e][n=128(j1|j3)][k=512]
__device__ __nv_bfloat16 g_w13lo[(size_t)NEXP * 128 * DIMX];
__device__ __nv_bfloat16 g_w2hi[(size_t)NEXP * DIMX * INTER];  // [e][d=512][j=64]
__device__ __nv_bfloat16 g_w2lo[(size_t)NEXP * DIMX * INTER];

// ---------------- kernel A: fused prep (zero + split x/w13/w2) ----------------
__global__ __launch_bounds__(256) void prep_kernel(
    const float* __restrict__ x, const float* __restrict__ w1,
    const float* __restrict__ w3, const float* __restrict__ w2)
{
    int blk = blockIdx.x;
    int tid = threadIdx.x;

    if (blk >= 1568) {                      // ---- zero counters ----
        if (tid < NEXP) g_counts[tid] = 0;
        return;
    }
    if (blk < 512) {                        // ---- split x ----
        int i = (blk * 256 + tid) * 4;
        float4 v = *reinterpret_cast<const float4*>(x + i);
        __nv_bfloat162 h01 = __floats2bfloat162_rn(v.x, v.y);
        __nv_bfloat162 h23 = __floats2bfloat162_rn(v.z, v.w);
        __nv_bfloat162 l01 = __floats2bfloat162_rn(v.x - __bfloat162float(h01.x),
                                                   v.y - __bfloat162float(h01.y));
        __nv_bfloat162 l23 = __floats2bfloat162_rn(v.z - __bfloat162float(h23.x),
                                                   v.w - __bfloat162float(h23.y));
        *reinterpret_cast<__nv_bfloat162*>(g_xhi + i)     = h01;
        *reinterpret_cast<__nv_bfloat162*>(g_xhi + i + 2) = h23;
        *reinterpret_cast<__nv_bfloat162*>(g_xlo + i)     = l01;
        *reinterpret_cast<__nv_bfloat162*>(g_xlo + i + 2) = l23;
        return;
    }
    if (blk < 1040) {                       // ---- split + transpose W1||W3 ----
        int id = blk - 512;
        int e = id >> 3, kb = id & 7;
        __shared__ float T1[64][65], T3[64][65];
        #pragma unroll
        for (int q = 0; q < 16; q++) {
            int idx = tid + q * 256;
            int kk = idx >> 6, j = idx & 63;
            size_t s = ((size_t)e * DIMX + kb * 64 + kk) * INTER + j;
            T1[kk][j] = w1[s];
            T3[kk][j] = w3[s];
        }
        __syncthreads();
        #pragma unroll
        for (int q = 0; q < 16; q++) {
            int idx = tid + q * 256;
            int j = idx >> 6, kk = idx & 63;
            float v1 = T1[kk][j], v3 = T3[kk][j];
            __nv_bfloat16 h1 = __float2bfloat16(v1);
            __nv_bfloat16 h3 = __float2bfloat16(v3);
            size_t o1 = ((size_t)e * 128 + j) * DIMX + kb * 64 + kk;
            size_t o3 = ((size_t)e * 128 + 64 + j) * DIMX + kb * 64 + kk;
            g_w13hi[o1] = h1;
            g_w13hi[o3] = h3;
            g_w13lo[o1] = __float2bfloat16(v1 - __bfloat162float(h1));
            g_w13lo[o3] = __float2bfloat16(v3 - __bfloat162float(h3));
        }
        return;
    }
    {                                       // ---- split + transpose W2 ----
        int id = blk - 1040;
        int e = id >> 3, db = id & 7;
        __shared__ float T[64][65];
        #pragma unroll
        for (int q = 0; q < 16; q++) {
            int idx = tid + q * 256;
            int j = idx >> 6, d = idx & 63;
            T[j][d] = w2[((size_t)e * INTER + j) * DIMX + db * 64 + d];
        }
        __syncthreads();
        #pragma unroll
        for (int q = 0; q < 16; q++) {
            int idx = tid + q * 256;
            int d = idx >> 6, j = idx & 63;
            float v = T[j][d];
            __nv_bfloat16 h = __float2bfloat16(v);
            size_t o = ((size_t)e * DIMX + db * 64 + d) * INTER + j;
            g_w2hi[o] = h;
            g_w2lo[o] = __float2bfloat16(v - __bfloat162float(h));
        }
    }
}

// ---------------- kernel 1: gate (proven) ----------------
__global__ __launch_bounds__(256) void gate_kernel(
    const float* __restrict__ x, const float* __restrict__ gw,
    const float* __restrict__ bias)
{
    __shared__ float Xs[32][32];
    __shared__ float Gs[32][65];
    __shared__ float S[32][66];

    int tid  = threadIdx.x;
    int tok0 = blockIdx.x * 32;
    int tg   = tid >> 5;
    int lane = tid & 31;

    float acc[4][2] = {};

    for (int k0 = 0; k0 < DIMX; k0 += 32) {
        {
            int r = tid >> 3;
            int c = (tid & 7) * 4;
            float4 v = *reinterpret_cast<const float4*>(&x[(size_t)(tok0 + r) * DIMX + k0 + c]);
            Xs[r][c] = v.x; Xs[r][c+1] = v.y; Xs[r][c+2] = v.z; Xs[r][c+3] = v.w;
        }
        {
            int e  = tid >> 2;
            int kk = (tid & 3) * 8;
            float4 a = *reinterpret_cast<const float4*>(&gw[(size_t)e * DIMX + k0 + kk]);
            float4 b = *reinterpret_cast<const float4*>(&gw[(size_t)e * DIMX + k0 + kk + 4]);
            Gs[kk+0][e] = a.x; Gs[kk+1][e] = a.y; Gs[kk+2][e] = a.z; Gs[kk+3][e] = a.w;
            Gs[kk+4][e] = b.x; Gs[kk+5][e] = b.y; Gs[kk+6][e] = b.z; Gs[kk+7][e] = b.w;
        }
        __syncthreads();
        #pragma unroll
        for (int kk = 0; kk < 32; kk++) {
            float g0 = Gs[kk][lane], g1 = Gs[kk][lane + 32];
            #pragma unroll
            for (int i = 0; i < 4; i++) {
                float xv = Xs[tg * 4 + i][kk];
                acc[i][0] = fmaf(xv, g0, acc[i][0]);
                acc[i][1] = fmaf(xv, g1, acc[i][1]);
            }
        }
        __syncthreads();
    }
    #pragma unroll
    for (int i = 0; i < 4; i++) {
        S[tg * 4 + i][lane]      = acc[i][0];
        S[tg * 4 + i][lane + 32] = acc[i][1];
    }
    __syncthreads();

    float b0 = bias[lane], b1 = bias[lane + 32];
    for (int i = 0; i < 4; i++) {
        int t = tg * 4 + i;
        float s0 = S[t][lane], s1 = S[t][lane + 32];
        float mx = fmaxf(s0, s1);
        #pragma unroll
        for (int o = 16; o > 0; o >>= 1) mx = fmaxf(mx, __shfl_xor_sync(0xffffffffu, mx, o));
        float e0 = expf(s0 - mx), e1 = expf(s1 - mx);
        float z = e0 + e1;
        #pragma unroll
        for (int o = 16; o > 0; o >>= 1) z += __shfl_xor_sync(0xffffffffu, z, o);
        float inv = 1.0f / z;
        float p0 = e0 * inv, p1 = e1 * inv;
        float k0v = p0 + b0, k1v = p1 + b1;
        int gt = tok0 + t;
        for (int r = 0; r < TOPK; r++) {
            float key, pv; int idx;
            if (k0v >= k1v) { key = k0v; pv = p0; idx = lane; }
            else            { key = k1v; pv = p1; idx = lane + 32; }
            #pragma unroll
            for (int o = 16; o > 0; o >>= 1) {
                float ok = __shfl_xor_sync(0xffffffffu, key, o);
                float op = __shfl_xor_sync(0xffffffffu, pv,  o);
                int   oi = __shfl_xor_sync(0xffffffffu, idx, o);
                if (ok > key || (ok == key && oi < idx)) { key = ok; pv = op; idx = oi; }
            }
            if (lane == 0) {
                int slot = gt * KSLOT + NSH + r;
                g_eidx[slot] = idx + NSH;
                g_wt  [slot] = pv;
                g_pos [slot] = atomicAdd(&g_counts[idx + NSH], 1);
            }
            if (idx == lane)           k0v = -INFINITY;
            else if (idx == lane + 32) k1v = -INFINITY;
        }
        if (lane < NSH) {
            int slot = gt * KSLOT + lane;
            g_eidx[slot] = lane;
            g_wt  [slot] = 1.0f;
            g_pos [slot] = gt;
        }
    }
}

// ---------------- kernel B: fused scatter + scan ----------------
__global__ void scatscan_kernel() {
    if (blockIdx.x < 32) {
        int i = blockIdx.x * 256 + threadIdx.x;
        int e = g_eidx[i];
        g_perm[e * ECAP + g_pos[i]] = i;
    } else if (threadIdx.x == 0) {
        int nt = 0;
        for (int e = 0; e < NEXP; e++) {
            int c = (e < NSH) ? NTOK : g_counts[e];
            for (int j = 0; j < c; j += TILE_M) {
                g_tiles[nt] = make_int4(e, e * ECAP + j, min(TILE_M, c - j), 0);
                nt++;
            }
        }
        g_ntiles = nt;
    }
}

// ---------------- kernel 4: grouped expert FFN on mma.sync bf16 ----------------
// 128 threads (4 warps), static grid, 3 CTAs/SM target.
// smem 56KB: A hi/lo double-buffered (16K), B hi/lo single-buffered (32K), G (8K).
__global__ void __launch_bounds__(128, 3) ffn_mma_kernel()
{
    extern __shared__ __align__(16) char dyn[];
    __shared__ int   toks[TILE_M];
    __shared__ float wts[TILE_M];
    __shared__ int   slots[TILE_M];

    int bid = blockIdx.x;
    if (bid >= g_ntiles) return;
    int4 tl = g_tiles[bid];
    int e = tl.x, p0 = tl.y, m = tl.z;

    int tid = threadIdx.x, wid = tid >> 5, lane = tid & 31;

    uint32_t sb = smem_u32(dyn);
    uint32_t Ah[2] = { sb,          sb + 4096  };
    uint32_t Al[2] = { sb + 8192,   sb + 12288 };
    uint32_t Bh = sb + 16384;      // 16KB
    uint32_t Bl = sb + 32768;      // 16KB
    uint32_t Gh = sb + 49152, Gl = sb + 53248;

    if (tid < TILE_M) {
        int i = (tid < m) ? g_perm[p0 + tid] : g_perm[p0];
        slots[tid] = i; toks[tid] = i >> 3; wts[tid] = g_wt[i];
    }
    __syncthreads();

    const __nv_bfloat16* w13h = g_w13hi + (size_t)e * 128 * DIMX;
    const __nv_bfloat16* w13l = g_w13lo + (size_t)e * 128 * DIMX;
    const __nv_bfloat16* w2h  = g_w2hi  + (size_t)e * DIMX * INTER;
    const __nv_bfloat16* w2l  = g_w2lo  + (size_t)e * DIMX * INTER;

    auto stage_A = [&](const __nv_bfloat16* src, uint32_t dst, int kb) {
        #pragma unroll
        for (int q = 0; q < 2; q++) {
            int idx = tid + q * 128;
            int row = idx >> 3, c = idx & 7;
            cp16(dst + row * 128 + ((c ^ (row & 7)) << 4),
                 src + (size_t)toks[row] * DIMX + kb * 64 + c * 8);
        }
    };
    auto stage_B = [&](const __nv_bfloat16* src, uint32_t dst, int kb) {
        #pragma unroll
        for (int q = 0; q < 8; q++) {
            int idx = tid + q * 128;
            int row = idx >> 3, c = idx & 7;
            cp16(dst + row * 128 + ((c ^ (row & 7)) << 4),
                 src + (size_t)row * DIMX + kb * 64 + c * 8);
        }
    };
    auto stage_W2 = [&](const __nv_bfloat16* src, uint32_t dst, int chunk) {
        #pragma unroll
        for (int q = 0; q < 8; q++) {
            int idx = tid + q * 128;
            int row = idx >> 3, c = idx & 7;
            cp16(dst + row * 128 + ((c ^ (row & 7)) << 4),
                 src + (size_t)(chunk * 128 + row) * INTER + c * 8);
        }
    };

    auto addrA = [&](uint32_t base, int mt, int k0) {
        int row = mt * 16 + (lane & 15);
        int kc  = (k0 >> 3) + (lane >> 4);
        return base + row * 128 + (((uint32_t)kc ^ (row & 7)) << 4);
    };
    auto addrB = [&](uint32_t base, int nb, int k0) {
        int row = nb + (lane & 7) + ((lane >> 4) << 3);
        int kc  = (k0 >> 3) + ((lane >> 3) & 1);
        return base + row * 128 + (((uint32_t)kc ^ (row & 7)) << 4);
    };

    // ---- h-stage ----
    float acc[2][4][4] = {};

    stage_A(g_xhi, Ah[0], 0); stage_A(g_xlo, Al[0], 0);
    stage_B(w13h, Bh, 0);     stage_B(w13l, Bl, 0);
    cp_commit();

    #pragma unroll 1
    for (int kb = 0; kb < 8; kb++) {
        int ab = kb & 1;
        cp_wait<0>();
        __syncthreads();                 // A[ab] + B(kb) visible
        if (kb + 1 < 8) {                // A prefetch only (B buffer in use)
            stage_A(g_xhi, Ah[ab ^ 1], kb + 1);
            stage_A(g_xlo, Al[ab ^ 1], kb + 1);
            cp_commit();
        }

        #pragma unroll
        for (int pass = 0; pass < 3; pass++) {
            uint32_t Abase = (pass == 1) ? Al[ab] : Ah[ab];
            uint32_t Bbase = (pass == 2) ? Bl : Bh;
            #pragma unroll
            for (int ks = 0; ks < 4; ks++) {
                int k0 = ks * 16;
                uint32_t a0[4], a1[4], bt[4][2];
                ldsm4(a0[0], a0[1], a0[2], a0[3], addrA(Abase, 0, k0));
                ldsm4(a1[0], a1[1], a1[2], a1[3], addrA(Abase, 1, k0));
                {
                    uint32_t r0, r1, r2, r3;
                    ldsm4(r0, r1, r2, r3, addrB(Bbase, wid * 16, k0));
                    bt[0][0] = r0; bt[0][1] = r1; bt[1][0] = r2; bt[1][1] = r3;
                    ldsm4(r0, r1, r2, r3, addrB(Bbase, 64 + wid * 16, k0));
                    bt[2][0] = r0; bt[2][1] = r1; bt[3][0] = r2; bt[3][1] = r3;
                }
                #pragma unroll
                for (int nt = 0; nt < 4; nt++) {
                    mma_bf16(acc[0][nt], a0, bt[nt]);
                    mma_bf16(acc[1][nt], a1, bt[nt]);
                }
            }
        }
        __syncthreads();                 // all warps done reading B(kb)
        if (kb + 1 < 8) {
            stage_B(w13h, Bh, kb + 1);
            stage_B(w13l, Bl, kb + 1);
            cp_commit();
        }
    }

    // prefetch W2 chunk 0 into the (now free) B buffers while epilogue runs
    stage_W2(w2h, Bh, 0); stage_W2(w2l, Bl, 0);
    cp_commit();

    // ---- epilogue: g = silu(h1)*h3 -> Gh/Gl [32][64] swizzled ----
    {
        int rbase = lane >> 2, cbase = (lane & 3) * 2;
        #pragma unroll
        for (int mt = 0; mt < 2; mt++) {
            #pragma unroll
            for (int p = 0; p < 2; p++) {
                const float* h1 = acc[mt][p];
                const float* h3 = acc[mt][p + 2];
                #pragma unroll
                for (int half = 0; half < 2; half++) {
                    int row = mt * 16 + rbase + half * 8;
                    float v0 = h1[half * 2], v1 = h1[half * 2 + 1];
                    float g0 = v0 / (1.0f + __expf(-v0)) * h3[half * 2];
                    float g1 = v1 / (1.0f + __expf(-v1)) * h3[half * 2 + 1];
                    __nv_bfloat162 hh = __floats2bfloat162_rn(g0, g1);
                    __nv_bfloat162 ll = __floats2bfloat162_rn(g0 - __bfloat162float(hh.x),
                                                              g1 - __bfloat162float(hh.y));
                    int j = wid * 16 + p * 8 + cbase;
                    uint32_t off = row * 128 + (((uint32_t)(j >> 3) ^ (row & 7)) << 4)
                                   + (j & 7) * 2;
                    *reinterpret_cast<__nv_bfloat162*>((char*)dyn + (Gh - sb) + off) = hh;
                    *reinterpret_cast<__nv_bfloat162*>((char*)dyn + (Gl - sb) + off) = ll;
                }
            }
        }
    }

    // ---- W2 stage: 4 chunks of 128 d, single-buffered ----
    int rbase = lane >> 2, cbase = (lane & 3) * 2;
    #pragma unroll 1
    for (int c = 0; c < 4; c++) {
        cp_wait<0>();
        __syncthreads();                 // W2 chunk c + (c==0) G visible

        float oacc[2][4][4] = {};
        #pragma unroll
        for (int pass = 0; pass < 3; pass++) {
            uint32_t Abase = (pass == 1) ? Gl : Gh;
            uint32_t Bbase = (pass == 2) ? Bl : Bh;
            #pragma unroll
            for (int ks = 0; ks < 4; ks++) {
                int k0 = ks * 16;
                uint32_t a0[4], a1[4], bt[4][2];
                ldsm4(a0[0], a0[1], a0[2], a0[3], addrA(Abase, 0, k0));
                ldsm4(a1[0], a1[1], a1[2], a1[3], addrA(Abase, 1, k0));
                {
                    uint32_t r0, r1, r2, r3;
                    ldsm4(r0, r1, r2, r3, addrB(Bbase, wid * 32, k0));
                    bt[0][0] = r0; bt[0][1] = r1; bt[1][0] = r2; bt[1][1] = r3;
                    ldsm4(r0, r1, r2, r3, addrB(Bbase, wid * 32 + 16, k0));
                    bt[2][0] = r0; bt[2][1] = r1; bt[3][0] = r2; bt[3][1] = r3;
                }
                #pragma unroll
                for (int nt = 0; nt < 4; nt++) {
                    mma_bf16(oacc[0][nt], a0, bt[nt]);
                    mma_bf16(oacc[1][nt], a1, bt[nt]);
                }
            }
        }
        __syncthreads();                 // done reading B before restage
        if (c + 1 < 4) {
            stage_W2(w2h, Bh, c + 1);
            stage_W2(w2l, Bl, c + 1);
            cp_commit();
        }
        // write weighted outputs (overlaps next chunk's transfer)
        #pragma unroll
        for (int mt = 0; mt < 2; mt++) {
            #pragma unroll
            for (int half = 0; half < 2; half++) {
                int r = mt * 16 + rbase + half * 8;
                if (r < m) {
                    float wt = wts[r];
                    float* orow = g_slot_out + (size_t)slots[r] * DIMX;
                    #pragma unroll
                    for (int nt = 0; nt < 4; nt++) {
                        int col = c * 128 + wid * 32 + nt * 8 + cbase;
                        float2 v;
                        v.x = oacc[mt][nt][half * 2]     * wt;
                        v.y = oacc[mt][nt][half * 2 + 1] * wt;
                        *reinterpret_cast<float2*>(orow + col) = v;
                    }
                }
            }
        }
    }
}

// ---------------- kernel 5: combine ----------------
__global__ void combine_kernel(float* __restrict__ out) {
    int i = blockIdx.x * 256 + threadIdx.x;
    if (i >= NTOK * DIMX / 4) return;
    int t = i >> 7;
    int d4 = i & (DIMX/4 - 1);
    float4 s = make_float4(0.f, 0.f, 0.f, 0.f);
    #pragma unroll
    for (int sl = 0; sl < KSLOT; sl++) {
        const float4* p = reinterpret_cast<const float4*>(
            &g_slot_out[((size_t)(t * KSLOT + sl)) * DIMX]);
        float4 v = p[d4];
        s.x += v.x; s.y += v.y; s.z += v.z; s.w += v.w;
    }
    reinterpret_cast<float4*>(out)[i] = s;
}

// ---------------- launch ----------------
extern "C" void kernel_launch(void* const* d_in, const int* in_sizes, int n_in,
                              void* d_out, int out_size) {
    const float* x  = (const float*)d_in[0];
    const float* gw = (const float*)d_in[1];
    const float* gb = (const float*)d_in[2];
    const float* w1 = (const float*)d_in[3];
    const float* w2 = (const float*)d_in[4];
    const float* w3 = (const float*)d_in[5];
    float* out = (float*)d_out;

    const int ffn_smem = 57344;   // A 16K + B 32K + G 8K + pad
    cudaFuncSetAttribute(ffn_mma_kernel,
                         cudaFuncAttributeMaxDynamicSharedMemorySize, ffn_smem);

    prep_kernel<<<1569, 256>>>(x, w1, w3, w2);
    gate_kernel<<<NTOK / 32, 256>>>(x, gw, gb);
    scatscan_kernel<<<33, 256>>>();
    ffn_mma_kernel<<<MAXTILES, 128, ffn_smem>>>();
    combine_kernel<<<(NTOK * DIMX / 4) / 256, 256>>>(out);
}

// round 11
// speedup vs baseline: 1.3864x; 1.3864x over previous
#include <cuda_runtime.h>
#include <cuda_bf16.h>
#include <math.h>
#include <stdint.h>

// ---------------- problem constants ----------------
#define DIMX     512
#define INTER    64
#define NSH      2
#define NROUTED  64
#define NEXP     66
#define TOPK     6
#define KSLOT    8
#define NTOK     1024
#define NSLOT    (NTOK * KSLOT)
#define TILE_M   64
#define MAXTILES 224
#define ECAP     1024          // fixed per-expert segment capacity in g_perm

// ---------------- PTX helpers (sm_80-level only) ----------------
__device__ __forceinline__ uint32_t smem_u32(const void* p) {
    uint32_t a;
    asm("{ .reg .u64 t; cvta.to.shared.u64 t, %1; cvt.u32.u64 %0, t; }" : "=r"(a) : "l"(p));
    return a;
}
__device__ __forceinline__ void cp16(uint32_t sdst, const void* gsrc) {
    asm volatile("cp.async.cg.shared.global [%0], [%1], 16;" :: "r"(sdst), "l"(gsrc));
}
__device__ __forceinline__ void cp_commit() { asm volatile("cp.async.commit_group;"); }
template<int N> __device__ __forceinline__ void cp_wait() {
    asm volatile("cp.async.wait_group %0;" :: "n"(N));
}
__device__ __forceinline__ void ldsm4(uint32_t& r0, uint32_t& r1, uint32_t& r2, uint32_t& r3,
                                      uint32_t addr) {
    asm volatile("ldmatrix.sync.aligned.m8n8.x4.shared.b16 {%0,%1,%2,%3}, [%4];"
                 : "=r"(r0), "=r"(r1), "=r"(r2), "=r"(r3) : "r"(addr));
}
__device__ __forceinline__ void mma_bf16(float* c, const uint32_t* a, const uint32_t* b) {
    asm volatile(
        "mma.sync.aligned.m16n8k16.row.col.f32.bf16.bf16.f32 "
        "{%0,%1,%2,%3}, {%4,%5,%6,%7}, {%8,%9}, {%0,%1,%2,%3};"
        : "+f"(c[0]), "+f"(c[1]), "+f"(c[2]), "+f"(c[3])
        : "r"(a[0]), "r"(a[1]), "r"(a[2]), "r"(a[3]), "r"(b[0]), "r"(b[1]));
}

// ---------------- device scratch ----------------
__device__ int   g_eidx[NSLOT];
__device__ float g_wt[NSLOT];
__device__ int   g_pos[NSLOT];
__device__ int   g_counts[NEXP];
__device__ int   g_perm[NEXP * ECAP];
__device__ int4  g_tiles[MAXTILES];
__device__ int   g_ntiles;
__device__ float g_slot_out[(size_t)NSLOT * DIMX];

__device__ __nv_bfloat16 g_xhi[NTOK * DIMX];
__device__ __nv_bfloat16 g_xlo[NTOK * DIMX];
__device__ __nv_bfloat16 g_w13hi[(size_t)NEXP * 128 * DIMX];   // [e][n=128(j1|j3)][k=512]
__device__ __nv_bfloat16 g_w13lo[(size_t)NEXP * 128 * DIMX];
__device__ __nv_bfloat16 g_w2hi[(size_t)NEXP * DIMX * INTER];  // [e][d=512][j=64]
__device__ __nv_bfloat16 g_w2lo[(size_t)NEXP * DIMX * INTER];

// ---------------- kernel A: fused prep (zero + split x/w13/w2) ----------------
__global__ __launch_bounds__(256) void prep_kernel(
    const float* __restrict__ x, const float* __restrict__ w1,
    const float* __restrict__ w3, const float* __restrict__ w2)
{
    int blk = blockIdx.x;
    int tid = threadIdx.x;

    if (blk >= 1568) {
        if (tid < NEXP) g_counts[tid] = 0;
        return;
    }
    if (blk < 512) {                        // ---- split x ----
        int i = (blk * 256 + tid) * 4;
        float4 v = *reinterpret_cast<const float4*>(x + i);
        __nv_bfloat162 h01 = __floats2bfloat162_rn(v.x, v.y);
        __nv_bfloat162 h23 = __floats2bfloat162_rn(v.z, v.w);
        __nv_bfloat162 l01 = __floats2bfloat162_rn(v.x - __bfloat162float(h01.x),
                                                   v.y - __bfloat162float(h01.y));
        __nv_bfloat162 l23 = __floats2bfloat162_rn(v.z - __bfloat162float(h23.x),
                                                   v.w - __bfloat162float(h23.y));
        *reinterpret_cast<__nv_bfloat162*>(g_xhi + i)     = h01;
        *reinterpret_cast<__nv_bfloat162*>(g_xhi + i + 2) = h23;
        *reinterpret_cast<__nv_bfloat162*>(g_xlo + i)     = l01;
        *reinterpret_cast<__nv_bfloat162*>(g_xlo + i + 2) = l23;
        return;
    }
    if (blk < 1040) {                       // ---- split + transpose W1||W3 ----
        int id = blk - 512;
        int e = id >> 3, kb = id & 7;
        __shared__ float T1[64][65], T3[64][65];
        #pragma unroll
        for (int q = 0; q < 16; q++) {
            int idx = tid + q * 256;
            int kk = idx >> 6, j = idx & 63;
            size_t s = ((size_t)e * DIMX + kb * 64 + kk) * INTER + j;
            T1[kk][j] = w1[s];
            T3[kk][j] = w3[s];
        }
        __syncthreads();
        #pragma unroll
        for (int q = 0; q < 16; q++) {
            int idx = tid + q * 256;
            int j = idx >> 6, kk = idx & 63;
            float v1 = T1[kk][j], v3 = T3[kk][j];
            __nv_bfloat16 h1 = __float2bfloat16(v1);
            __nv_bfloat16 h3 = __float2bfloat16(v3);
            size_t o1 = ((size_t)e * 128 + j) * DIMX + kb * 64 + kk;
            size_t o3 = ((size_t)e * 128 + 64 + j) * DIMX + kb * 64 + kk;
            g_w13hi[o1] = h1;
            g_w13hi[o3] = h3;
            g_w13lo[o1] = __float2bfloat16(v1 - __bfloat162float(h1));
            g_w13lo[o3] = __float2bfloat16(v3 - __bfloat162float(h3));
        }
        return;
    }
    {                                       // ---- split + transpose W2 ----
        int id = blk - 1040;
        int e = id >> 3, db = id & 7;
        __shared__ float T[64][65];
        #pragma unroll
        for (int q = 0; q < 16; q++) {
            int idx = tid + q * 256;
            int j = idx >> 6, d = idx & 63;
            T[j][d] = w2[((size_t)e * INTER + j) * DIMX + db * 64 + d];
        }
        __syncthreads();
        #pragma unroll
        for (int q = 0; q < 16; q++) {
            int idx = tid + q * 256;
            int d = idx >> 6, j = idx & 63;
            float v = T[j][d];
            __nv_bfloat16 h = __float2bfloat16(v);
            size_t o = ((size_t)e * DIMX + db * 64 + d) * INTER + j;
            g_w2hi[o] = h;
            g_w2lo[o] = __float2bfloat16(v - __bfloat162float(h));
        }
    }
}

// ---------------- kernel 1: gate (proven) ----------------
__global__ __launch_bounds__(256) void gate_kernel(
    const float* __restrict__ x, const float* __restrict__ gw,
    const float* __restrict__ bias)
{
    __shared__ float Xs[32][32];
    __shared__ float Gs[32][65];
    __shared__ float S[32][66];

    int tid  = threadIdx.x;
    int tok0 = blockIdx.x * 32;
    int tg   = tid >> 5;
    int lane = tid & 31;

    float acc[4][2] = {};

    for (int k0 = 0; k0 < DIMX; k0 += 32) {
        {
            int r = tid >> 3;
            int c = (tid & 7) * 4;
            float4 v = *reinterpret_cast<const float4*>(&x[(size_t)(tok0 + r) * DIMX + k0 + c]);
            Xs[r][c] = v.x; Xs[r][c+1] = v.y; Xs[r][c+2] = v.z; Xs[r][c+3] = v.w;
        }
        {
            int e  = tid >> 2;
            int kk = (tid & 3) * 8;
            float4 a = *reinterpret_cast<const float4*>(&gw[(size_t)e * DIMX + k0 + kk]);
            float4 b = *reinterpret_cast<const float4*>(&gw[(size_t)e * DIMX + k0 + kk + 4]);
            Gs[kk+0][e] = a.x; Gs[kk+1][e] = a.y; Gs[kk+2][e] = a.z; Gs[kk+3][e] = a.w;
            Gs[kk+4][e] = b.x; Gs[kk+5][e] = b.y; Gs[kk+6][e] = b.z; Gs[kk+7][e] = b.w;
        }
        __syncthreads();
        #pragma unroll
        for (int kk = 0; kk < 32; kk++) {
            float g0 = Gs[kk][lane], g1 = Gs[kk][lane + 32];
            #pragma unroll
            for (int i = 0; i < 4; i++) {
                float xv = Xs[tg * 4 + i][kk];
                acc[i][0] = fmaf(xv, g0, acc[i][0]);
                acc[i][1] = fmaf(xv, g1, acc[i][1]);
            }
        }
        __syncthreads();
    }
    #pragma unroll
    for (int i = 0; i < 4; i++) {
        S[tg * 4 + i][lane]      = acc[i][0];
        S[tg * 4 + i][lane + 32] = acc[i][1];
    }
    __syncthreads();

    float b0 = bias[lane], b1 = bias[lane + 32];
    for (int i = 0; i < 4; i++) {
        int t = tg * 4 + i;
        float s0 = S[t][lane], s1 = S[t][lane + 32];
        float mx = fmaxf(s0, s1);
        #pragma unroll
        for (int o = 16; o > 0; o >>= 1) mx = fmaxf(mx, __shfl_xor_sync(0xffffffffu, mx, o));
        float e0 = expf(s0 - mx), e1 = expf(s1 - mx);
        float z = e0 + e1;
        #pragma unroll
        for (int o = 16; o > 0; o >>= 1) z += __shfl_xor_sync(0xffffffffu, z, o);
        float inv = 1.0f / z;
        float p0 = e0 * inv, p1 = e1 * inv;
        float k0v = p0 + b0, k1v = p1 + b1;
        int gt = tok0 + t;
        for (int r = 0; r < TOPK; r++) {
            float key, pv; int idx;
            if (k0v >= k1v) { key = k0v; pv = p0; idx = lane; }
            else            { key = k1v; pv = p1; idx = lane + 32; }
            #pragma unroll
            for (int o = 16; o > 0; o >>= 1) {
                float ok = __shfl_xor_sync(0xffffffffu, key, o);
                float op = __shfl_xor_sync(0xffffffffu, pv,  o);
                int   oi = __shfl_xor_sync(0xffffffffu, idx, o);
                if (ok > key || (ok == key && oi < idx)) { key = ok; pv = op; idx = oi; }
            }
            if (lane == 0) {
                int slot = gt * KSLOT + NSH + r;
                g_eidx[slot] = idx + NSH;
                g_wt  [slot] = pv;
                g_pos [slot] = atomicAdd(&g_counts[idx + NSH], 1);
            }
            if (idx == lane)           k0v = -INFINITY;
            else if (idx == lane + 32) k1v = -INFINITY;
        }
        if (lane < NSH) {
            int slot = gt * KSLOT + lane;
            g_eidx[slot] = lane;
            g_wt  [slot] = 1.0f;
            g_pos [slot] = gt;
        }
    }
}

// ---------------- kernel B: fused scatter + scan ----------------
__global__ void scatscan_kernel() {
    if (blockIdx.x < 32) {
        int i = blockIdx.x * 256 + threadIdx.x;
        int e = g_eidx[i];
        g_perm[e * ECAP + g_pos[i]] = i;
    } else if (threadIdx.x == 0) {
        int nt = 0;
        for (int e = 0; e < NEXP; e++) {
            int c = (e < NSH) ? NTOK : g_counts[e];
            for (int j = 0; j < c; j += TILE_M) {
                g_tiles[nt] = make_int4(e, e * ECAP + j, min(TILE_M, c - j), 0);
                nt++;
            }
        }
        g_ntiles = nt;
    }
}

// ---------------- kernel 4: grouped expert FFN on mma.sync bf16, M=64 tiles ----------------
// 128 threads (4 warps). A: [64 tok][64 k] hi/lo double-buffered (32K).
// B: [128 n][64 k] hi/lo double-buffered (64K). G aliases the A region after h-stage.
__global__ void __launch_bounds__(128, 2) ffn_mma_kernel()
{
    extern __shared__ __align__(16) char dyn[];
    __shared__ int   toks[TILE_M];
    __shared__ float wts[TILE_M];
    __shared__ int   slots[TILE_M];

    int bid = blockIdx.x;
    if (bid >= g_ntiles) return;
    int4 tl = g_tiles[bid];
    int e = tl.x, p0 = tl.y, m = tl.z;

    int tid = threadIdx.x, wid = tid >> 5, lane = tid & 31;

    uint32_t sb = smem_u32(dyn);
    uint32_t Ah[2] = { sb,          sb + 8192  };
    uint32_t Al[2] = { sb + 16384,  sb + 24576 };
    uint32_t Bh[2] = { sb + 32768,  sb + 49152 };
    uint32_t Bl[2] = { sb + 65536,  sb + 81920 };
    uint32_t Gh = sb, Gl = sb + 16384;          // alias A region (dead after h-stage)

    if (tid < TILE_M) {
        int i = (tid < m) ? g_perm[p0 + tid] : g_perm[p0];
        slots[tid] = i; toks[tid] = i >> 3; wts[tid] = g_wt[i];
    }
    __syncthreads();

    const __nv_bfloat16* w13h = g_w13hi + (size_t)e * 128 * DIMX;
    const __nv_bfloat16* w13l = g_w13lo + (size_t)e * 128 * DIMX;
    const __nv_bfloat16* w2h  = g_w2hi  + (size_t)e * DIMX * INTER;
    const __nv_bfloat16* w2l  = g_w2lo  + (size_t)e * DIMX * INTER;

    auto stage_A = [&](const __nv_bfloat16* src, uint32_t dst, int kb) {
        #pragma unroll
        for (int q = 0; q < 4; q++) {
            int idx = tid + q * 128;          // 0..511
            int row = idx >> 3, c = idx & 7;
            cp16(dst + row * 128 + ((c ^ (row & 7)) << 4),
                 src + (size_t)toks[row] * DIMX + kb * 64 + c * 8);
        }
    };
    auto stage_B = [&](const __nv_bfloat16* src, uint32_t dst, int kb) {
        #pragma unroll
        for (int q = 0; q < 8; q++) {
            int idx = tid + q * 128;          // 0..1023
            int row = idx >> 3, c = idx & 7;
            cp16(dst + row * 128 + ((c ^ (row & 7)) << 4),
                 src + (size_t)row * DIMX + kb * 64 + c * 8);
        }
    };
    auto stage_W2 = [&](const __nv_bfloat16* src, uint32_t dst, int chunk) {
        #pragma unroll
        for (int q = 0; q < 8; q++) {
            int idx = tid + q * 128;
            int row = idx >> 3, c = idx & 7;
            cp16(dst + row * 128 + ((c ^ (row & 7)) << 4),
                 src + (size_t)(chunk * 128 + row) * INTER + c * 8);
        }
    };

    auto addrA = [&](uint32_t base, int mt, int k0) {
        int row = mt * 16 + (lane & 15);
        int kc  = (k0 >> 3) + (lane >> 4);
        return base + row * 128 + (((uint32_t)kc ^ (row & 7)) << 4);
    };
    auto addrB = [&](uint32_t base, int nb, int k0) {
        int row = nb + (lane & 7) + ((lane >> 4) << 3);
        int kc  = (k0 >> 3) + ((lane >> 3) & 1);
        return base + row * 128 + (((uint32_t)kc ^ (row & 7)) << 4);
    };

    // ---- h-stage: acc[mt 0..3][nt]: nt 0,1 = h1 cols wid*16+{0,8}; nt 2,3 = h3 ----
    float acc[4][4][4] = {};

    stage_A(g_xhi, Ah[0], 0); stage_A(g_xlo, Al[0], 0);
    stage_B(w13h, Bh[0], 0);  stage_B(w13l, Bl[0], 0);
    cp_commit();

    #pragma unroll 1
    for (int kb = 0; kb < 8; kb++) {
        int b = kb & 1;
        if (kb + 1 < 8) {
            int nb = b ^ 1;
            stage_A(g_xhi, Ah[nb], kb + 1); stage_A(g_xlo, Al[nb], kb + 1);
            stage_B(w13h, Bh[nb], kb + 1);  stage_B(w13l, Bl[nb], kb + 1);
            cp_commit();
            cp_wait<1>();
        } else {
            cp_wait<0>();
        }
        __syncthreads();

        #pragma unroll
        for (int pass = 0; pass < 3; pass++) {
            uint32_t Abase = (pass == 1) ? Al[b] : Ah[b];
            uint32_t Bbase = (pass == 2) ? Bl[b] : Bh[b];
            #pragma unroll
            for (int ks = 0; ks < 4; ks++) {
                int k0 = ks * 16;
                uint32_t a[4][4], bt[4][2];
                #pragma unroll
                for (int mt = 0; mt < 4; mt++)
                    ldsm4(a[mt][0], a[mt][1], a[mt][2], a[mt][3], addrA(Abase, mt, k0));
                {
                    uint32_t r0, r1, r2, r3;
                    ldsm4(r0, r1, r2, r3, addrB(Bbase, wid * 16, k0));
                    bt[0][0] = r0; bt[0][1] = r1; bt[1][0] = r2; bt[1][1] = r3;
                    ldsm4(r0, r1, r2, r3, addrB(Bbase, 64 + wid * 16, k0));
                    bt[2][0] = r0; bt[2][1] = r1; bt[3][0] = r2; bt[3][1] = r3;
                }
                #pragma unroll
                for (int mt = 0; mt < 4; mt++)
                    #pragma unroll
                    for (int nt = 0; nt < 4; nt++)
                        mma_bf16(acc[mt][nt], a[mt], bt[nt]);
            }
        }
        __syncthreads();
    }

    // prefetch W2 chunk 0 into B buffers while epilogue runs
    stage_W2(w2h, Bh[0], 0); stage_W2(w2l, Bl[0], 0);
    cp_commit();

    // ---- epilogue: g = silu(h1)*h3 -> Gh/Gl [64][64] swizzled (aliases A region) ----
    {
        int rbase = lane >> 2, cbase = (lane & 3) * 2;
        #pragma unroll
        for (int mt = 0; mt < 4; mt++) {
            #pragma unroll
            for (int p = 0; p < 2; p++) {
                const float* h1 = acc[mt][p];
                const float* h3 = acc[mt][p + 2];
                #pragma unroll
                for (int half = 0; half < 2; half++) {
                    int row = mt * 16 + rbase + half * 8;
                    float v0 = h1[half * 2], v1 = h1[half * 2 + 1];
                    float g0 = v0 / (1.0f + __expf(-v0)) * h3[half * 2];
                    float g1 = v1 / (1.0f + __expf(-v1)) * h3[half * 2 + 1];
                    __nv_bfloat162 hh = __floats2bfloat162_rn(g0, g1);
                    __nv_bfloat162 ll = __floats2bfloat162_rn(g0 - __bfloat162float(hh.x),
                                                              g1 - __bfloat162float(hh.y));
                    int j = wid * 16 + p * 8 + cbase;
                    uint32_t off = row * 128 + (((uint32_t)(j >> 3) ^ (row & 7)) << 4)
                                   + (j & 7) * 2;
                    *reinterpret_cast<__nv_bfloat162*>((char*)dyn + (Gh - sb) + off) = hh;
                    *reinterpret_cast<__nv_bfloat162*>((char*)dyn + (Gl - sb) + off) = ll;
                }
            }
        }
    }
    __syncthreads();

    // ---- W2 stage: 4 chunks of 128 d, double-buffered ----
    int rbase = lane >> 2, cbase = (lane & 3) * 2;
    #pragma unroll 1
    for (int c = 0; c < 4; c++) {
        int b = c & 1;
        if (c + 1 < 4) {
            int nb = b ^ 1;
            stage_W2(w2h, Bh[nb], c + 1); stage_W2(w2l, Bl[nb], c + 1);
            cp_commit();
            cp_wait<1>();
        } else {
            cp_wait<0>();
        }
        __syncthreads();

        float oacc[4][4][4] = {};
        #pragma unroll
        for (int pass = 0; pass < 3; pass++) {
            uint32_t Abase = (pass == 1) ? Gl : Gh;
            uint32_t Bbase = (pass == 2) ? Bl[b] : Bh[b];
            #pragma unroll
            for (int ks = 0; ks < 4; ks++) {
                int k0 = ks * 16;
                uint32_t a[4][4], bt[4][2];
                #pragma unroll
                for (int mt = 0; mt < 4; mt++)
                    ldsm4(a[mt][0], a[mt][1], a[mt][2], a[mt][3], addrA(Abase, mt, k0));
                {
                    uint32_t r0, r1, r2, r3;
                    ldsm4(r0, r1, r2, r3, addrB(Bbase, wid * 32, k0));
                    bt[0][0] = r0; bt[0][1] = r1; bt[1][0] = r2; bt[1][1] = r3;
                    ldsm4(r0, r1, r2, r3, addrB(Bbase, wid * 32 + 16, k0));
                    bt[2][0] = r0; bt[2][1] = r1; bt[3][0] = r2; bt[3][1] = r3;
                }
                #pragma unroll
                for (int mt = 0; mt < 4; mt++)
                    #pragma unroll
                    for (int nt = 0; nt < 4; nt++)
                        mma_bf16(oacc[mt][nt], a[mt], bt[nt]);
            }
        }
        // write weighted outputs
        #pragma unroll
        for (int mt = 0; mt < 4; mt++) {
            #pragma unroll
            for (int half = 0; half < 2; half++) {
                int r = mt * 16 + rbase + half * 8;
                if (r < m) {
                    float wt = wts[r];
                    float* orow = g_slot_out + (size_t)slots[r] * DIMX;
                    #pragma unroll
                    for (int nt = 0; nt < 4; nt++) {
                        int col = c * 128 + wid * 32 + nt * 8 + cbase;
                        float2 v;
                        v.x = oacc[mt][nt][half * 2]     * wt;
                        v.y = oacc[mt][nt][half * 2 + 1] * wt;
                        *reinterpret_cast<float2*>(orow + col) = v;
                    }
                }
            }
        }
        __syncthreads();
    }
}

// ---------------- kernel 5: combine ----------------
__global__ void combine_kernel(float* __restrict__ out) {
    int i = blockIdx.x * 256 + threadIdx.x;
    if (i >= NTOK * DIMX / 4) return;
    int t = i >> 7;
    int d4 = i & (DIMX/4 - 1);
    float4 s = make_float4(0.f, 0.f, 0.f, 0.f);
    #pragma unroll
    for (int sl = 0; sl < KSLOT; sl++) {
        const float4* p = reinterpret_cast<const float4*>(
            &g_slot_out[((size_t)(t * KSLOT + sl)) * DIMX]);
        float4 v = p[d4];
        s.x += v.x; s.y += v.y; s.z += v.z; s.w += v.w;
    }
    reinterpret_cast<float4*>(out)[i] = s;
}

// ---------------- launch ----------------
extern "C" void kernel_launch(void* const* d_in, const int* in_sizes, int n_in,
                              void* d_out, int out_size) {
    const float* x  = (const float*)d_in[0];
    const float* gw = (const float*)d_in[1];
    const float* gb = (const float*)d_in[2];
    const float* w1 = (const float*)d_in[3];
    const float* w2 = (const float*)d_in[4];
    const float* w3 = (const float*)d_in[5];
    float* out = (float*)d_out;

    const int ffn_smem = 98304;   // A 32K (G aliased) + B 64K
    cudaFuncSetAttribute(ffn_mma_kernel,
                         cudaFuncAttributeMaxDynamicSharedMemorySize, ffn_smem);

    prep_kernel<<<1569, 256>>>(x, w1, w3, w2);
    gate_kernel<<<NTOK / 32, 256>>>(x, gw, gb);
    scatscan_kernel<<<33, 256>>>();
    ffn_mma_kernel<<<MAXTILES, 128, ffn_smem>>>();
    combine_kernel<<<(NTOK * DIMX / 4) / 256, 256>>>(out);
}

// round 12
// speedup vs baseline: 1.5355x; 1.1075x over previous
#include <cuda_runtime.h>
#include <cuda_bf16.h>
#include <math.h>
#include <stdint.h>

// ---------------- problem constants ----------------
#define DIMX     512
#define INTER    64
#define NSH      2
#define NROUTED  64
#define NEXP     66
#define TOPK     6
#define KSLOT    8
#define NTOK     1024
#define NSLOT    (NTOK * KSLOT)
#define TILE_M   32
#define MAXTILES 320
#define ECAP     1024          // fixed per-expert segment capacity in g_perm

// ---------------- PTX helpers (sm_80-level only) ----------------
__device__ __forceinline__ uint32_t smem_u32(const void* p) {
    uint32_t a;
    asm("{ .reg .u64 t; cvta.to.shared.u64 t, %1; cvt.u32.u64 %0, t; }" : "=r"(a) : "l"(p));
    return a;
}
__device__ __forceinline__ void cp16(uint32_t sdst, const void* gsrc) {
    asm volatile("cp.async.cg.shared.global [%0], [%1], 16;" :: "r"(sdst), "l"(gsrc));
}
__device__ __forceinline__ void cp_commit() { asm volatile("cp.async.commit_group;"); }
template<int N> __device__ __forceinline__ void cp_wait() {
    asm volatile("cp.async.wait_group %0;" :: "n"(N));
}
__device__ __forceinline__ void ldsm4(uint32_t& r0, uint32_t& r1, uint32_t& r2, uint32_t& r3,
                                      uint32_t addr) {
    asm volatile("ldmatrix.sync.aligned.m8n8.x4.shared.b16 {%0,%1,%2,%3}, [%4];"
                 : "=r"(r0), "=r"(r1), "=r"(r2), "=r"(r3) : "r"(addr));
}
__device__ __forceinline__ void mma_bf16(float* c, const uint32_t* a, const uint32_t* b) {
    asm volatile(
        "mma.sync.aligned.m16n8k16.row.col.f32.bf16.bf16.f32 "
        "{%0,%1,%2,%3}, {%4,%5,%6,%7}, {%8,%9}, {%0,%1,%2,%3};"
        : "+f"(c[0]), "+f"(c[1]), "+f"(c[2]), "+f"(c[3])
        : "r"(a[0]), "r"(a[1]), "r"(a[2]), "r"(a[3]), "r"(b[0]), "r"(b[1]));
}

// ---------------- device scratch ----------------
__device__ int   g_eidx[NSLOT];
__device__ float g_wt[NSLOT];
__device__ int   g_pos[NSLOT];
__device__ int   g_counts[NEXP];
__device__ int   g_perm[NEXP * ECAP];
__device__ int4  g_tiles[MAXTILES];
__device__ int   g_ntiles;
__device__ float g_slot_out[(size_t)NSLOT * DIMX];

__device__ __nv_bfloat16 g_xhi[NTOK * DIMX];
__device__ __nv_bfloat16 g_xlo[NTOK * DIMX];
__device__ __nv_bfloat16 g_w13hi[(size_t)NEXP * 128 * DIMX];   // [e][n=128(j1|j3)][k=512]
__device__ __nv_bfloat16 g_w13lo[(size_t)NEXP * 128 * DIMX];
__device__ __nv_bfloat16 g_w2hi[(size_t)NEXP * DIMX * INTER];  // [e][d=512][j=64]
__device__ __nv_bfloat16 g_w2lo[(size_t)NEXP * DIMX * INTER];

// ---------------- kernel A: fused prep (zero + split x/w13/w2) ----------------
__global__ __launch_bounds__(256) void prep_kernel(
    const float* __restrict__ x, const float* __restrict__ w1,
    const float* __restrict__ w3, const float* __restrict__ w2)
{
    int blk = blockIdx.x;
    int tid = threadIdx.x;

    if (blk >= 1568) {
        if (tid < NEXP) g_counts[tid] = 0;
        return;
    }
    if (blk < 512) {                        // ---- split x ----
        int i = (blk * 256 + tid) * 4;
        float4 v = *reinterpret_cast<const float4*>(x + i);
        __nv_bfloat162 h01 = __floats2bfloat162_rn(v.x, v.y);
        __nv_bfloat162 h23 = __floats2bfloat162_rn(v.z, v.w);
        __nv_bfloat162 l01 = __floats2bfloat162_rn(v.x - __bfloat162float(h01.x),
                                                   v.y - __bfloat162float(h01.y));
        __nv_bfloat162 l23 = __floats2bfloat162_rn(v.z - __bfloat162float(h23.x),
                                                   v.w - __bfloat162float(h23.y));
        *reinterpret_cast<__nv_bfloat162*>(g_xhi + i)     = h01;
        *reinterpret_cast<__nv_bfloat162*>(g_xhi + i + 2) = h23;
        *reinterpret_cast<__nv_bfloat162*>(g_xlo + i)     = l01;
        *reinterpret_cast<__nv_bfloat162*>(g_xlo + i + 2) = l23;
        return;
    }
    if (blk < 1040) {                       // ---- split + transpose W1||W3 ----
        int id = blk - 512;
        int e = id >> 3, kb = id & 7;
        __shared__ float T1[64][65], T3[64][65];
        #pragma unroll
        for (int q = 0; q < 16; q++) {
            int idx = tid + q * 256;
            int kk = idx >> 6, j = idx & 63;
            size_t s = ((size_t)e * DIMX + kb * 64 + kk) * INTER + j;
            T1[kk][j] = w1[s];
            T3[kk][j] = w3[s];
        }
        __syncthreads();
        #pragma unroll
        for (int q = 0; q < 16; q++) {
            int idx = tid + q * 256;
            int j = idx >> 6, kk = idx & 63;
            float v1 = T1[kk][j], v3 = T3[kk][j];
            __nv_bfloat16 h1 = __float2bfloat16(v1);
            __nv_bfloat16 h3 = __float2bfloat16(v3);
            size_t o1 = ((size_t)e * 128 + j) * DIMX + kb * 64 + kk;
            size_t o3 = ((size_t)e * 128 + 64 + j) * DIMX + kb * 64 + kk;
            g_w13hi[o1] = h1;
            g_w13hi[o3] = h3;
            g_w13lo[o1] = __float2bfloat16(v1 - __bfloat162float(h1));
            g_w13lo[o3] = __float2bfloat16(v3 - __bfloat162float(h3));
        }
        return;
    }
    {                                       // ---- split + transpose W2 ----
        int id = blk - 1040;
        int e = id >> 3, db = id & 7;
        __shared__ float T[64][65];
        #pragma unroll
        for (int q = 0; q < 16; q++) {
            int idx = tid + q * 256;
            int j = idx >> 6, d = idx & 63;
            T[j][d] = w2[((size_t)e * INTER + j) * DIMX + db * 64 + d];
        }
        __syncthreads();
        #pragma unroll
        for (int q = 0; q < 16; q++) {
            int idx = tid + q * 256;
            int d = idx >> 6, j = idx & 63;
            float v = T[j][d];
            __nv_bfloat16 h = __float2bfloat16(v);
            size_t o = ((size_t)e * DIMX + db * 64 + d) * INTER + j;
            g_w2hi[o] = h;
            g_w2lo[o] = __float2bfloat16(v - __bfloat162float(h));
        }
    }
}

// ---------------- kernel 1: gate (proven) ----------------
__global__ __launch_bounds__(256) void gate_kernel(
    const float* __restrict__ x, const float* __restrict__ gw,
    const float* __restrict__ bias)
{
    __shared__ float Xs[32][32];
    __shared__ float Gs[32][65];
    __shared__ float S[32][66];

    int tid  = threadIdx.x;
    int tok0 = blockIdx.x * 32;
    int tg   = tid >> 5;
    int lane = tid & 31;

    float acc[4][2] = {};

    for (int k0 = 0; k0 < DIMX; k0 += 32) {
        {
            int r = tid >> 3;
            int c = (tid & 7) * 4;
            float4 v = *reinterpret_cast<const float4*>(&x[(size_t)(tok0 + r) * DIMX + k0 + c]);
            Xs[r][c] = v.x; Xs[r][c+1] = v.y; Xs[r][c+2] = v.z; Xs[r][c+3] = v.w;
        }
        {
            int e  = tid >> 2;
            int kk = (tid & 3) * 8;
            float4 a = *reinterpret_cast<const float4*>(&gw[(size_t)e * DIMX + k0 + kk]);
            float4 b = *reinterpret_cast<const float4*>(&gw[(size_t)e * DIMX + k0 + kk + 4]);
            Gs[kk+0][e] = a.x; Gs[kk+1][e] = a.y; Gs[kk+2][e] = a.z; Gs[kk+3][e] = a.w;
            Gs[kk+4][e] = b.x; Gs[kk+5][e] = b.y; Gs[kk+6][e] = b.z; Gs[kk+7][e] = b.w;
        }
        __syncthreads();
        #pragma unroll
        for (int kk = 0; kk < 32; kk++) {
            float g0 = Gs[kk][lane], g1 = Gs[kk][lane + 32];
            #pragma unroll
            for (int i = 0; i < 4; i++) {
                float xv = Xs[tg * 4 + i][kk];
                acc[i][0] = fmaf(xv, g0, acc[i][0]);
                acc[i][1] = fmaf(xv, g1, acc[i][1]);
            }
        }
        __syncthreads();
    }
    #pragma unroll
    for (int i = 0; i < 4; i++) {
        S[tg * 4 + i][lane]      = acc[i][0];
        S[tg * 4 + i][lane + 32] = acc[i][1];
    }
    __syncthreads();

    float b0 = bias[lane], b1 = bias[lane + 32];
    for (int i = 0; i < 4; i++) {
        int t = tg * 4 + i;
        float s0 = S[t][lane], s1 = S[t][lane + 32];
        float mx = fmaxf(s0, s1);
        #pragma unroll
        for (int o = 16; o > 0; o >>= 1) mx = fmaxf(mx, __shfl_xor_sync(0xffffffffu, mx, o));
        float e0 = expf(s0 - mx), e1 = expf(s1 - mx);
        float z = e0 + e1;
        #pragma unroll
        for (int o = 16; o > 0; o >>= 1) z += __shfl_xor_sync(0xffffffffu, z, o);
        float inv = 1.0f / z;
        float p0 = e0 * inv, p1 = e1 * inv;
        float k0v = p0 + b0, k1v = p1 + b1;
        int gt = tok0 + t;
        for (int r = 0; r < TOPK; r++) {
            float key, pv; int idx;
            if (k0v >= k1v) { key = k0v; pv = p0; idx = lane; }
            else            { key = k1v; pv = p1; idx = lane + 32; }
            #pragma unroll
            for (int o = 16; o > 0; o >>= 1) {
                float ok = __shfl_xor_sync(0xffffffffu, key, o);
                float op = __shfl_xor_sync(0xffffffffu, pv,  o);
                int   oi = __shfl_xor_sync(0xffffffffu, idx, o);
                if (ok > key || (ok == key && oi < idx)) { key = ok; pv = op; idx = oi; }
            }
            if (lane == 0) {
                int slot = gt * KSLOT + NSH + r;
                g_eidx[slot] = idx + NSH;
                g_wt  [slot] = pv;
                g_pos [slot] = atomicAdd(&g_counts[idx + NSH], 1);
            }
            if (idx == lane)           k0v = -INFINITY;
            else if (idx == lane + 32) k1v = -INFINITY;
        }
        if (lane < NSH) {
            int slot = gt * KSLOT + lane;
            g_eidx[slot] = lane;
            g_wt  [slot] = 1.0f;
            g_pos [slot] = gt;
        }
    }
}

// ---------------- kernel B: fused scatter + scan ----------------
__global__ void scatscan_kernel() {
    if (blockIdx.x < 32) {
        int i = blockIdx.x * 256 + threadIdx.x;
        int e = g_eidx[i];
        g_perm[e * ECAP + g_pos[i]] = i;
    } else if (threadIdx.x == 0) {
        int nt = 0;
        for (int e = 0; e < NEXP; e++) {
            int c = (e < NSH) ? NTOK : g_counts[e];
            for (int j = 0; j < c; j += TILE_M) {
                g_tiles[nt] = make_int4(e, e * ECAP + j, min(TILE_M, c - j), 0);
                nt++;
            }
        }
        g_ntiles = nt;
    }
}

// ---------------- kernel 4: grouped expert FFN on mma.sync bf16 ----------------
// 256 threads (8 warps), TILE_M = 32. mg = wid>>2 picks 16-token half,
// nw = wid&3 picks the N slice. Full double buffering, same smem as the 84.4us kernel.
__global__ void __launch_bounds__(256, 2) ffn_mma_kernel()
{
    extern __shared__ __align__(16) char dyn[];
    __shared__ int   toks[TILE_M];
    __shared__ float wts[TILE_M];
    __shared__ int   slots[TILE_M];

    int bid = blockIdx.x;
    if (bid >= g_ntiles) return;
    int4 tl = g_tiles[bid];
    int e = tl.x, p0 = tl.y, m = tl.z;

    int tid = threadIdx.x, wid = tid >> 5, lane = tid & 31;
    int mg = wid >> 2;          // token half 0/1
    int nw = wid & 3;           // N slice

    uint32_t sb = smem_u32(dyn);
    uint32_t Ah[2] = { sb,          sb + 4096  };
    uint32_t Al[2] = { sb + 8192,   sb + 12288 };
    uint32_t Bh[2] = { sb + 16384,  sb + 32768 };
    uint32_t Bl[2] = { sb + 49152,  sb + 65536 };
    uint32_t Gh = sb + 81920, Gl = sb + 86016;

    if (tid < TILE_M) {
        int i = (tid < m) ? g_perm[p0 + tid] : g_perm[p0];
        slots[tid] = i; toks[tid] = i >> 3; wts[tid] = g_wt[i];
    }
    __syncthreads();

    const __nv_bfloat16* w13h = g_w13hi + (size_t)e * 128 * DIMX;
    const __nv_bfloat16* w13l = g_w13lo + (size_t)e * 128 * DIMX;
    const __nv_bfloat16* w2h  = g_w2hi  + (size_t)e * DIMX * INTER;
    const __nv_bfloat16* w2l  = g_w2lo  + (size_t)e * DIMX * INTER;

    // ---- staging helpers (swizzled 16B chunks, 256 threads) ----
    auto stage_A = [&](const __nv_bfloat16* src, uint32_t dst, int kb) {
        int row = tid >> 3, c = tid & 7;          // 256 chunks exactly
        cp16(dst + row * 128 + ((c ^ (row & 7)) << 4),
             src + (size_t)toks[row] * DIMX + kb * 64 + c * 8);
    };
    auto stage_B = [&](const __nv_bfloat16* src, uint32_t dst, int kb) {
        #pragma unroll
        for (int q = 0; q < 4; q++) {
            int idx = tid + q * 256;              // 0..1023
            int row = idx >> 3, c = idx & 7;
            cp16(dst + row * 128 + ((c ^ (row & 7)) << 4),
                 src + (size_t)row * DIMX + kb * 64 + c * 8);
        }
    };
    auto stage_W2 = [&](const __nv_bfloat16* src, uint32_t dst, int chunk) {
        #pragma unroll
        for (int q = 0; q < 4; q++) {
            int idx = tid + q * 256;
            int row = idx >> 3, c = idx & 7;
            cp16(dst + row * 128 + ((c ^ (row & 7)) << 4),
                 src + (size_t)(chunk * 128 + row) * INTER + c * 8);
        }
    };

    auto addrA = [&](uint32_t base, int mt, int k0) {
        int row = mt * 16 + (lane & 15);
        int kc  = (k0 >> 3) + (lane >> 4);
        return base + row * 128 + (((uint32_t)kc ^ (row & 7)) << 4);
    };
    auto addrB = [&](uint32_t base, int nb, int k0) {
        int row = nb + (lane & 7) + ((lane >> 4) << 3);
        int kc  = (k0 >> 3) + ((lane >> 3) & 1);
        return base + row * 128 + (((uint32_t)kc ^ (row & 7)) << 4);
    };

    // ---- h-stage: acc[nt]: nt 0,1 = h1 cols nw*16+{0,8}; nt 2,3 = h3 ----
    float acc[4][4] = {};

    stage_A(g_xhi, Ah[0], 0); stage_A(g_xlo, Al[0], 0);
    stage_B(w13h, Bh[0], 0);  stage_B(w13l, Bl[0], 0);
    cp_commit();

    #pragma unroll 1
    for (int kb = 0; kb < 8; kb++) {
        int b = kb & 1;
        if (kb + 1 < 8) {
            int nb = b ^ 1;
            stage_A(g_xhi, Ah[nb], kb + 1); stage_A(g_xlo, Al[nb], kb + 1);
            stage_B(w13h, Bh[nb], kb + 1);  stage_B(w13l, Bl[nb], kb + 1);
            cp_commit();
            cp_wait<1>();
        } else {
            cp_wait<0>();
        }
        __syncthreads();

        #pragma unroll
        for (int pass = 0; pass < 3; pass++) {
            uint32_t Abase = (pass == 1) ? Al[b] : Ah[b];
            uint32_t Bbase = (pass == 2) ? Bl[b] : Bh[b];
            #pragma unroll
            for (int ks = 0; ks < 4; ks++) {
                int k0 = ks * 16;
                uint32_t a[4], bt[4][2];
                ldsm4(a[0], a[1], a[2], a[3], addrA(Abase, mg, k0));
                {
                    uint32_t r0, r1, r2, r3;
                    ldsm4(r0, r1, r2, r3, addrB(Bbase, nw * 16, k0));
                    bt[0][0] = r0; bt[0][1] = r1; bt[1][0] = r2; bt[1][1] = r3;
                    ldsm4(r0, r1, r2, r3, addrB(Bbase, 64 + nw * 16, k0));
                    bt[2][0] = r0; bt[2][1] = r1; bt[3][0] = r2; bt[3][1] = r3;
                }
                #pragma unroll
                for (int nt = 0; nt < 4; nt++)
                    mma_bf16(acc[nt], a, bt[nt]);
            }
        }
        __syncthreads();
    }

    // prefetch W2 chunk 0 into the (now free) B buffers while epilogue runs
    stage_W2(w2h, Bh[0], 0); stage_W2(w2l, Bl[0], 0);
    cp_commit();

    // ---- epilogue: g = silu(h1)*h3 -> Gh/Gl [32][64] swizzled ----
    {
        int rbase = lane >> 2, cbase = (lane & 3) * 2;
        #pragma unroll
        for (int p = 0; p < 2; p++) {
            const float* h1 = acc[p];
            const float* h3 = acc[p + 2];
            #pragma unroll
            for (int half = 0; half < 2; half++) {
                int row = mg * 16 + rbase + half * 8;
                float v0 = h1[half * 2], v1 = h1[half * 2 + 1];
                float g0 = v0 / (1.0f + __expf(-v0)) * h3[half * 2];
                float g1 = v1 / (1.0f + __expf(-v1)) * h3[half * 2 + 1];
                __nv_bfloat162 hh = __floats2bfloat162_rn(g0, g1);
                __nv_bfloat162 ll = __floats2bfloat162_rn(g0 - __bfloat162float(hh.x),
                                                          g1 - __bfloat162float(hh.y));
                int j = nw * 16 + p * 8 + cbase;
                uint32_t off = row * 128 + (((uint32_t)(j >> 3) ^ (row & 7)) << 4)
                               + (j & 7) * 2;
                *reinterpret_cast<__nv_bfloat162*>((char*)dyn + (Gh - sb) + off) = hh;
                *reinterpret_cast<__nv_bfloat162*>((char*)dyn + (Gl - sb) + off) = ll;
            }
        }
    }
    __syncthreads();

    // ---- W2 stage: 4 chunks of 128 d, double-buffered ----
    int rbase = lane >> 2, cbase = (lane & 3) * 2;
    #pragma unroll 1
    for (int c = 0; c < 4; c++) {
        int b = c & 1;
        if (c + 1 < 4) {
            int nb = b ^ 1;
            stage_W2(w2h, Bh[nb], c + 1); stage_W2(w2l, Bl[nb], c + 1);
            cp_commit();
            cp_wait<1>();
        } else {
            cp_wait<0>();
        }
        __syncthreads();

        float oacc[4][4] = {};
        #pragma unroll
        for (int pass = 0; pass < 3; pass++) {
            uint32_t Abase = (pass == 1) ? Gl : Gh;
            uint32_t Bbase = (pass == 2) ? Bl[b] : Bh[b];
            #pragma unroll
            for (int ks = 0; ks < 4; ks++) {
                int k0 = ks * 16;
                uint32_t a[4], bt[4][2];
                ldsm4(a[0], a[1], a[2], a[3], addrA(Abase, mg, k0));
                {
                    uint32_t r0, r1, r2, r3;
                    ldsm4(r0, r1, r2, r3, addrB(Bbase, nw * 32, k0));
                    bt[0][0] = r0; bt[0][1] = r1; bt[1][0] = r2; bt[1][1] = r3;
                    ldsm4(r0, r1, r2, r3, addrB(Bbase, nw * 32 + 16, k0));
                    bt[2][0] = r0; bt[2][1] = r1; bt[3][0] = r2; bt[3][1] = r3;
                }
                #pragma unroll
                for (int nt = 0; nt < 4; nt++)
                    mma_bf16(oacc[nt], a, bt[nt]);
            }
        }
        // write weighted outputs
        #pragma unroll
        for (int half = 0; half < 2; half++) {
            int r = mg * 16 + rbase + half * 8;
            if (r < m) {
                float wt = wts[r];
                float* orow = g_slot_out + (size_t)slots[r] * DIMX;
                #pragma unroll
                for (int nt = 0; nt < 4; nt++) {
                    int col = c * 128 + nw * 32 + nt * 8 + cbase;
                    float2 v;
                    v.x = oacc[nt][half * 2]     * wt;
                    v.y = oacc[nt][half * 2 + 1] * wt;
                    *reinterpret_cast<float2*>(orow + col) = v;
                }
            }
        }
        __syncthreads();
    }
}

// ---------------- kernel 5: combine ----------------
__global__ void combine_kernel(float* __restrict__ out) {
    int i = blockIdx.x * 256 + threadIdx.x;
    if (i >= NTOK * DIMX / 4) return;
    int t = i >> 7;
    int d4 = i & (DIMX/4 - 1);
    float4 s = make_float4(0.f, 0.f, 0.f, 0.f);
    #pragma unroll
    for (int sl = 0; sl < KSLOT; sl++) {
        const float4* p = reinterpret_cast<const float4*>(
            &g_slot_out[((size_t)(t * KSLOT + sl)) * DIMX]);
        float4 v = p[d4];
        s.x += v.x; s.y += v.y; s.z += v.z; s.w += v.w;
    }
    reinterpret_cast<float4*>(out)[i] = s;
}

// ---------------- launch ----------------
extern "C" void kernel_launch(void* const* d_in, const int* in_sizes, int n_in,
                              void* d_out, int out_size) {
    const float* x  = (const float*)d_in[0];
    const float* gw = (const float*)d_in[1];
    const float* gb = (const float*)d_in[2];
    const float* w1 = (const float*)d_in[3];
    const float* w2 = (const float*)d_in[4];
    const float* w3 = (const float*)d_in[5];
    float* out = (float*)d_out;

    const int ffn_smem = 90112;   // A 16K + B 64K + G 8K + pad
    cudaFuncSetAttribute(ffn_mma_kernel,
                         cudaFuncAttributeMaxDynamicSharedMemorySize, ffn_smem);

    prep_kernel<<<1569, 256>>>(x, w1, w3, w2);
    gate_kernel<<<NTOK / 32, 256>>>(x, gw, gb);
    scatscan_kernel<<<33, 256>>>();
    ffn_mma_kernel<<<MAXTILES, 256, ffn_smem>>>();
    combine_kernel<<<(NTOK * DIMX / 4) / 256, 256>>>(out);
}

// round 13
// speedup vs baseline: 1.8341x; 1.1945x over previous
#include <cuda_runtime.h>
#include <cuda_fp16.h>
#include <math.h>
#include <stdint.h>

// ---------------- problem constants ----------------
#define DIMX     512
#define INTER    64
#define NSH      2
#define NROUTED  64
#define NEXP     66
#define TOPK     6
#define KSLOT    8
#define NTOK     1024
#define NSLOT    (NTOK * KSLOT)
#define TILE_M   32
#define MAXTILES 320
#define ECAP     1024          // fixed per-expert segment capacity in g_perm

// ---------------- PTX helpers (sm_80-level only) ----------------
__device__ __forceinline__ uint32_t smem_u32(const void* p) {
    uint32_t a;
    asm("{ .reg .u64 t; cvta.to.shared.u64 t, %1; cvt.u32.u64 %0, t; }" : "=r"(a) : "l"(p));
    return a;
}
__device__ __forceinline__ void cp16(uint32_t sdst, const void* gsrc) {
    asm volatile("cp.async.cg.shared.global [%0], [%1], 16;" :: "r"(sdst), "l"(gsrc));
}
__device__ __forceinline__ void cp_commit() { asm volatile("cp.async.commit_group;"); }
template<int N> __device__ __forceinline__ void cp_wait() {
    asm volatile("cp.async.wait_group %0;" :: "n"(N));
}
__device__ __forceinline__ void ldsm4(uint32_t& r0, uint32_t& r1, uint32_t& r2, uint32_t& r3,
                                      uint32_t addr) {
    asm volatile("ldmatrix.sync.aligned.m8n8.x4.shared.b16 {%0,%1,%2,%3}, [%4];"
                 : "=r"(r0), "=r"(r1), "=r"(r2), "=r"(r3) : "r"(addr));
}
__device__ __forceinline__ void mma_fp16(float* c, const uint32_t* a, const uint32_t* b) {
    asm volatile(
        "mma.sync.aligned.m16n8k16.row.col.f32.f16.f16.f32 "
        "{%0,%1,%2,%3}, {%4,%5,%6,%7}, {%8,%9}, {%0,%1,%2,%3};"
        : "+f"(c[0]), "+f"(c[1]), "+f"(c[2]), "+f"(c[3])
        : "r"(a[0]), "r"(a[1]), "r"(a[2]), "r"(a[3]), "r"(b[0]), "r"(b[1]));
}

// ---------------- device scratch ----------------
__device__ int   g_eidx[NSLOT];
__device__ float g_wt[NSLOT];
__device__ int   g_pos[NSLOT];
__device__ int   g_counts[NEXP];
__device__ int   g_perm[NEXP * ECAP];
__device__ int4  g_tiles[MAXTILES];
__device__ int   g_ntiles;
__device__ float g_slot_out[(size_t)NSLOT * DIMX];

__device__ __half g_xhi[NTOK * DIMX];
__device__ __half g_xlo[NTOK * DIMX];
__device__ __half g_w13h[(size_t)NEXP * 128 * DIMX];   // [e][n=128(j1|j3)][k=512] fp16
__device__ __half g_w2h[(size_t)NEXP * DIMX * INTER];  // [e][d=512][j=64] fp16

// ---------------- kernel A: fused prep (zero + split x + cvt w13/w2) ----------------
__global__ __launch_bounds__(256) void prep_kernel(
    const float* __restrict__ x, const float* __restrict__ w1,
    const float* __restrict__ w3, const float* __restrict__ w2)
{
    int blk = blockIdx.x;
    int tid = threadIdx.x;

    if (blk >= 1568) {
        if (tid < NEXP) g_counts[tid] = 0;
        return;
    }
    if (blk < 512) {                        // ---- split x into fp16 hi/lo ----
        int i = (blk * 256 + tid) * 4;
        float4 v = *reinterpret_cast<const float4*>(x + i);
        __half h0 = __float2half_rn(v.x), h1 = __float2half_rn(v.y);
        __half h2 = __float2half_rn(v.z), h3 = __float2half_rn(v.w);
        __half l0 = __float2half_rn(v.x - __half2float(h0));
        __half l1 = __float2half_rn(v.y - __half2float(h1));
        __half l2 = __float2half_rn(v.z - __half2float(h2));
        __half l3 = __float2half_rn(v.w - __half2float(h3));
        *reinterpret_cast<__half2*>(g_xhi + i)     = __halves2half2(h0, h1);
        *reinterpret_cast<__half2*>(g_xhi + i + 2) = __halves2half2(h2, h3);
        *reinterpret_cast<__half2*>(g_xlo + i)     = __halves2half2(l0, l1);
        *reinterpret_cast<__half2*>(g_xlo + i + 2) = __halves2half2(l2, l3);
        return;
    }
    if (blk < 1040) {                       // ---- transpose + cvt W1||W3 ----
        int id = blk - 512;
        int e = id >> 3, kb = id & 7;
        __shared__ float T1[64][65], T3[64][65];
        #pragma unroll
        for (int q = 0; q < 16; q++) {
            int idx = tid + q * 256;
            int kk = idx >> 6, j = idx & 63;
            size_t s = ((size_t)e * DIMX + kb * 64 + kk) * INTER + j;
            T1[kk][j] = w1[s];
            T3[kk][j] = w3[s];
        }
        __syncthreads();
        #pragma unroll
        for (int q = 0; q < 16; q++) {
            int idx = tid + q * 256;
            int j = idx >> 6, kk = idx & 63;
            size_t o1 = ((size_t)e * 128 + j) * DIMX + kb * 64 + kk;
            size_t o3 = ((size_t)e * 128 + 64 + j) * DIMX + kb * 64 + kk;
            g_w13h[o1] = __float2half_rn(T1[kk][j]);
            g_w13h[o3] = __float2half_rn(T3[kk][j]);
        }
        return;
    }
    {                                       // ---- transpose + cvt W2 ----
        int id = blk - 1040;
        int e = id >> 3, db = id & 7;
        __shared__ float T[64][65];
        #pragma unroll
        for (int q = 0; q < 16; q++) {
            int idx = tid + q * 256;
            int j = idx >> 6, d = idx & 63;
            T[j][d] = w2[((size_t)e * INTER + j) * DIMX + db * 64 + d];
        }
        __syncthreads();
        #pragma unroll
        for (int q = 0; q < 16; q++) {
            int idx = tid + q * 256;
            int d = idx >> 6, j = idx & 63;
            size_t o = ((size_t)e * DIMX + db * 64 + d) * INTER + j;
            g_w2h[o] = __float2half_rn(T[j][d]);
        }
    }
}

// ---------------- kernel 1: gate (proven) ----------------
__global__ __launch_bounds__(256) void gate_kernel(
    const float* __restrict__ x, const float* __restrict__ gw,
    const float* __restrict__ bias)
{
    __shared__ float Xs[32][32];
    __shared__ float Gs[32][65];
    __shared__ float S[32][66];

    int tid  = threadIdx.x;
    int tok0 = blockIdx.x * 32;
    int tg   = tid >> 5;
    int lane = tid & 31;

    float acc[4][2] = {};

    for (int k0 = 0; k0 < DIMX; k0 += 32) {
        {
            int r = tid >> 3;
            int c = (tid & 7) * 4;
            float4 v = *reinterpret_cast<const float4*>(&x[(size_t)(tok0 + r) * DIMX + k0 + c]);
            Xs[r][c] = v.x; Xs[r][c+1] = v.y; Xs[r][c+2] = v.z; Xs[r][c+3] = v.w;
        }
        {
            int e  = tid >> 2;
            int kk = (tid & 3) * 8;
            float4 a = *reinterpret_cast<const float4*>(&gw[(size_t)e * DIMX + k0 + kk]);
            float4 b = *reinterpret_cast<const float4*>(&gw[(size_t)e * DIMX + k0 + kk + 4]);
            Gs[kk+0][e] = a.x; Gs[kk+1][e] = a.y; Gs[kk+2][e] = a.z; Gs[kk+3][e] = a.w;
            Gs[kk+4][e] = b.x; Gs[kk+5][e] = b.y; Gs[kk+6][e] = b.z; Gs[kk+7][e] = b.w;
        }
        __syncthreads();
        #pragma unroll
        for (int kk = 0; kk < 32; kk++) {
            float g0 = Gs[kk][lane], g1 = Gs[kk][lane + 32];
            #pragma unroll
            for (int i = 0; i < 4; i++) {
                float xv = Xs[tg * 4 + i][kk];
                acc[i][0] = fmaf(xv, g0, acc[i][0]);
                acc[i][1] = fmaf(xv, g1, acc[i][1]);
            }
        }
        __syncthreads();
    }
    #pragma unroll
    for (int i = 0; i < 4; i++) {
        S[tg * 4 + i][lane]      = acc[i][0];
        S[tg * 4 + i][lane + 32] = acc[i][1];
    }
    __syncthreads();

    float b0 = bias[lane], b1 = bias[lane + 32];
    for (int i = 0; i < 4; i++) {
        int t = tg * 4 + i;
        float s0 = S[t][lane], s1 = S[t][lane + 32];
        float mx = fmaxf(s0, s1);
        #pragma unroll
        for (int o = 16; o > 0; o >>= 1) mx = fmaxf(mx, __shfl_xor_sync(0xffffffffu, mx, o));
        float e0 = expf(s0 - mx), e1 = expf(s1 - mx);
        float z = e0 + e1;
        #pragma unroll
        for (int o = 16; o > 0; o >>= 1) z += __shfl_xor_sync(0xffffffffu, z, o);
        float inv = 1.0f / z;
        float p0 = e0 * inv, p1 = e1 * inv;
        float k0v = p0 + b0, k1v = p1 + b1;
        int gt = tok0 + t;
        for (int r = 0; r < TOPK; r++) {
            float key, pv; int idx;
            if (k0v >= k1v) { key = k0v; pv = p0; idx = lane; }
            else            { key = k1v; pv = p1; idx = lane + 32; }
            #pragma unroll
            for (int o = 16; o > 0; o >>= 1) {
                float ok = __shfl_xor_sync(0xffffffffu, key, o);
                float op = __shfl_xor_sync(0xffffffffu, pv,  o);
                int   oi = __shfl_xor_sync(0xffffffffu, idx, o);
                if (ok > key || (ok == key && oi < idx)) { key = ok; pv = op; idx = oi; }
            }
            if (lane == 0) {
                int slot = gt * KSLOT + NSH + r;
                g_eidx[slot] = idx + NSH;
                g_wt  [slot] = pv;
                g_pos [slot] = atomicAdd(&g_counts[idx + NSH], 1);
            }
            if (idx == lane)           k0v = -INFINITY;
            else if (idx == lane + 32) k1v = -INFINITY;
        }
        if (lane < NSH) {
            int slot = gt * KSLOT + lane;
            g_eidx[slot] = lane;
            g_wt  [slot] = 1.0f;
            g_pos [slot] = gt;
        }
    }
}

// ---------------- kernel B: fused scatter + scan ----------------
__global__ void scatscan_kernel() {
    if (blockIdx.x < 32) {
        int i = blockIdx.x * 256 + threadIdx.x;
        int e = g_eidx[i];
        g_perm[e * ECAP + g_pos[i]] = i;
    } else if (threadIdx.x == 0) {
        int nt = 0;
        for (int e = 0; e < NEXP; e++) {
            int c = (e < NSH) ? NTOK : g_counts[e];
            for (int j = 0; j < c; j += TILE_M) {
                g_tiles[nt] = make_int4(e, e * ECAP + j, min(TILE_M, c - j), 0);
                nt++;
            }
        }
        g_ntiles = nt;
    }
}

// ---------------- kernel 4: grouped expert FFN, fp16 2-pass mma.sync ----------------
// 256 threads (8 warps), TILE_M=32. mg = wid>>2 token half, nw = wid&3 N slice.
// smem 56KB: A hi/lo double-buffered (16K), B fp16 double-buffered (32K), G hi/lo (8K).
__global__ void __launch_bounds__(256, 2) ffn_mma_kernel()
{
    extern __shared__ __align__(16) char dyn[];
    __shared__ int   toks[TILE_M];
    __shared__ float wts[TILE_M];
    __shared__ int   slots[TILE_M];

    int bid = blockIdx.x;
    if (bid >= g_ntiles) return;
    int4 tl = g_tiles[bid];
    int e = tl.x, p0 = tl.y, m = tl.z;

    int tid = threadIdx.x, wid = tid >> 5, lane = tid & 31;
    int mg = wid >> 2;          // token half 0/1
    int nw = wid & 3;           // N slice

    uint32_t sb = smem_u32(dyn);
    uint32_t Ah[2] = { sb,          sb + 4096  };
    uint32_t Al[2] = { sb + 8192,   sb + 12288 };
    uint32_t Bh[2] = { sb + 16384,  sb + 32768 };
    uint32_t Gh = sb + 49152, Gl = sb + 53248;

    if (tid < TILE_M) {
        int i = (tid < m) ? g_perm[p0 + tid] : g_perm[p0];
        slots[tid] = i; toks[tid] = i >> 3; wts[tid] = g_wt[i];
    }
    __syncthreads();

    const __half* w13 = g_w13h + (size_t)e * 128 * DIMX;
    const __half* w2e = g_w2h  + (size_t)e * DIMX * INTER;

    // ---- staging helpers (swizzled 16B chunks, 256 threads) ----
    auto stage_A = [&](const __half* src, uint32_t dst, int kb) {
        int row = tid >> 3, c = tid & 7;          // 256 chunks exactly
        cp16(dst + row * 128 + ((c ^ (row & 7)) << 4),
             src + (size_t)toks[row] * DIMX + kb * 64 + c * 8);
    };
    auto stage_B = [&](const __half* src, uint32_t dst, int kb) {
        #pragma unroll
        for (int q = 0; q < 4; q++) {
            int idx = tid + q * 256;              // 0..1023
            int row = idx >> 3, c = idx & 7;
            cp16(dst + row * 128 + ((c ^ (row & 7)) << 4),
                 src + (size_t)row * DIMX + kb * 64 + c * 8);
        }
    };
    auto stage_W2 = [&](const __half* src, uint32_t dst, int chunk) {
        #pragma unroll
        for (int q = 0; q < 4; q++) {
            int idx = tid + q * 256;
            int row = idx >> 3, c = idx & 7;
            cp16(dst + row * 128 + ((c ^ (row & 7)) << 4),
                 src + (size_t)(chunk * 128 + row) * INTER + c * 8);
        }
    };

    auto addrA = [&](uint32_t base, int mt, int k0) {
        int row = mt * 16 + (lane & 15);
        int kc  = (k0 >> 3) + (lane >> 4);
        return base + row * 128 + (((uint32_t)kc ^ (row & 7)) << 4);
    };
    auto addrB = [&](uint32_t base, int nb, int k0) {
        int row = nb + (lane & 7) + ((lane >> 4) << 3);
        int kc  = (k0 >> 3) + ((lane >> 3) & 1);
        return base + row * 128 + (((uint32_t)kc ^ (row & 7)) << 4);
    };

    // ---- h-stage: acc[nt]: nt 0,1 = h1 cols nw*16+{0,8}; nt 2,3 = h3 ----
    float acc[4][4] = {};

    stage_A(g_xhi, Ah[0], 0); stage_A(g_xlo, Al[0], 0);
    stage_B(w13, Bh[0], 0);
    cp_commit();

    #pragma unroll 1
    for (int kb = 0; kb < 8; kb++) {
        int b = kb & 1;
        if (kb + 1 < 8) {
            int nb = b ^ 1;
            stage_A(g_xhi, Ah[nb], kb + 1); stage_A(g_xlo, Al[nb], kb + 1);
            stage_B(w13, Bh[nb], kb + 1);
            cp_commit();
            cp_wait<1>();
        } else {
            cp_wait<0>();
        }
        __syncthreads();

        #pragma unroll
        for (int pass = 0; pass < 2; pass++) {
            uint32_t Abase = pass ? Al[b] : Ah[b];
            uint32_t Bbase = Bh[b];
            #pragma unroll
            for (int ks = 0; ks < 4; ks++) {
                int k0 = ks * 16;
                uint32_t a[4], bt[4][2];
                ldsm4(a[0], a[1], a[2], a[3], addrA(Abase, mg, k0));
                {
                    uint32_t r0, r1, r2, r3;
                    ldsm4(r0, r1, r2, r3, addrB(Bbase, nw * 16, k0));
                    bt[0][0] = r0; bt[0][1] = r1; bt[1][0] = r2; bt[1][1] = r3;
                    ldsm4(r0, r1, r2, r3, addrB(Bbase, 64 + nw * 16, k0));
                    bt[2][0] = r0; bt[2][1] = r1; bt[3][0] = r2; bt[3][1] = r3;
                }
                #pragma unroll
                for (int nt = 0; nt < 4; nt++)
                    mma_fp16(acc[nt], a, bt[nt]);
            }
        }
        __syncthreads();
    }

    // prefetch W2 chunk 0 into the (now free) B buffer while epilogue runs
    stage_W2(w2e, Bh[0], 0);
    cp_commit();

    // ---- epilogue: g = silu(h1)*h3 -> Gh/Gl [32][64] fp16 swizzled ----
    {
        int rbase = lane >> 2, cbase = (lane & 3) * 2;
        #pragma unroll
        for (int p = 0; p < 2; p++) {
            const float* h1 = acc[p];
            const float* h3 = acc[p + 2];
            #pragma unroll
            for (int half = 0; half < 2; half++) {
                int row = mg * 16 + rbase + half * 8;
                float v0 = h1[half * 2], v1 = h1[half * 2 + 1];
                float g0 = v0 / (1.0f + __expf(-v0)) * h3[half * 2];
                float g1 = v1 / (1.0f + __expf(-v1)) * h3[half * 2 + 1];
                __half h0 = __float2half_rn(g0), h1h = __float2half_rn(g1);
                __half l0 = __float2half_rn(g0 - __half2float(h0));
                __half l1 = __float2half_rn(g1 - __half2float(h1h));
                int j = nw * 16 + p * 8 + cbase;
                uint32_t off = row * 128 + (((uint32_t)(j >> 3) ^ (row & 7)) << 4)
                               + (j & 7) * 2;
                *reinterpret_cast<__half2*>((char*)dyn + (Gh - sb) + off) = __halves2half2(h0, h1h);
                *reinterpret_cast<__half2*>((char*)dyn + (Gl - sb) + off) = __halves2half2(l0, l1);
            }
        }
    }
    __syncthreads();

    // ---- W2 stage: 4 chunks of 128 d, double-buffered, 2 passes ----
    int rbase = lane >> 2, cbase = (lane & 3) * 2;
    #pragma unroll 1
    for (int c = 0; c < 4; c++) {
        int b = c & 1;
        if (c + 1 < 4) {
            int nb = b ^ 1;
            stage_W2(w2e, Bh[nb], c + 1);
            cp_commit();
            cp_wait<1>();
        } else {
            cp_wait<0>();
        }
        __syncthreads();

        float oacc[4][4] = {};
        #pragma unroll
        for (int pass = 0; pass < 2; pass++) {
            uint32_t Abase = pass ? Gl : Gh;
            uint32_t Bbase = Bh[b];
            #pragma unroll
            for (int ks = 0; ks < 4; ks++) {
                int k0 = ks * 16;
                uint32_t a[4], bt[4][2];
                ldsm4(a[0], a[1], a[2], a[3], addrA(Abase, mg, k0));
                {
                    uint32_t r0, r1, r2, r3;
                    ldsm4(r0, r1, r2, r3, addrB(Bbase, nw * 32, k0));
                    bt[0][0] = r0; bt[0][1] = r1; bt[1][0] = r2; bt[1][1] = r3;
                    ldsm4(r0, r1, r2, r3, addrB(Bbase, nw * 32 + 16, k0));
                    bt[2][0] = r0; bt[2][1] = r1; bt[3][0] = r2; bt[3][1] = r3;
                }
                #pragma unroll
                for (int nt = 0; nt < 4; nt++)
                    mma_fp16(oacc[nt], a, bt[nt]);
            }
        }
        // write weighted outputs
        #pragma unroll
        for (int half = 0; half < 2; half++) {
            int r = mg * 16 + rbase + half * 8;
            if (r < m) {
                float wt = wts[r];
                float* orow = g_slot_out + (size_t)slots[r] * DIMX;
                #pragma unroll
                for (int nt = 0; nt < 4; nt++) {
                    int col = c * 128 + nw * 32 + nt * 8 + cbase;
                    float2 v;
                    v.x = oacc[nt][half * 2]     * wt;
                    v.y = oacc[nt][half * 2 + 1] * wt;
                    *reinterpret_cast<float2*>(orow + col) = v;
                }
            }
        }
        __syncthreads();
    }
}

// ---------------- kernel 5: combine ----------------
__global__ void combine_kernel(float* __restrict__ out) {
    int i = blockIdx.x * 256 + threadIdx.x;
    if (i >= NTOK * DIMX / 4) return;
    int t = i >> 7;
    int d4 = i & (DIMX/4 - 1);
    float4 s = make_float4(0.f, 0.f, 0.f, 0.f);
    #pragma unroll
    for (int sl = 0; sl < KSLOT; sl++) {
        const float4* p = reinterpret_cast<const float4*>(
            &g_slot_out[((size_t)(t * KSLOT + sl)) * DIMX]);
        float4 v = p[d4];
        s.x += v.x; s.y += v.y; s.z += v.z; s.w += v.w;
    }
    reinterpret_cast<float4*>(out)[i] = s;
}

// ---------------- launch ----------------
extern "C" void kernel_launch(void* const* d_in, const int* in_sizes, int n_in,
                              void* d_out, int out_size) {
    const float* x  = (const float*)d_in[0];
    const float* gw = (const float*)d_in[1];
    const float* gb = (const float*)d_in[2];
    const float* w1 = (const float*)d_in[3];
    const float* w2 = (const float*)d_in[4];
    const float* w3 = (const float*)d_in[5];
    float* out = (float*)d_out;

    const int ffn_smem = 57344;   // A 16K + B 32K + G 8K
    cudaFuncSetAttribute(ffn_mma_kernel,
                         cudaFuncAttributeMaxDynamicSharedMemorySize, ffn_smem);

    prep_kernel<<<1569, 256>>>(x, w1, w3, w2);
    gate_kernel<<<NTOK / 32, 256>>>(x, gw, gb);
    scatscan_kernel<<<33, 256>>>();
    ffn_mma_kernel<<<MAXTILES, 256, ffn_smem>>>();
    combine_kernel<<<(NTOK * DIMX / 4) / 256, 256>>>(out);
}

// round 14
// speedup vs baseline: 2.2060x; 1.2028x over previous
#include <cuda_runtime.h>
#include <cuda_fp16.h>
#include <math.h>
#include <stdint.h>

// ---------------- problem constants ----------------
#define DIMX     512
#define INTER    64
#define NSH      2
#define NROUTED  64
#define NEXP     66
#define TOPK     6
#define KSLOT    8
#define NTOK     1024
#define NSLOT    (NTOK * KSLOT)
#define TILE_M   32
#define MAXTILES 320
#define ECAP     1024          // fixed per-expert segment capacity in g_perm

// ---------------- PTX helpers (sm_80-level only) ----------------
__device__ __forceinline__ uint32_t smem_u32(const void* p) {
    uint32_t a;
    asm("{ .reg .u64 t; cvta.to.shared.u64 t, %1; cvt.u32.u64 %0, t; }" : "=r"(a) : "l"(p));
    return a;
}
__device__ __forceinline__ void cp16(uint32_t sdst, const void* gsrc) {
    asm volatile("cp.async.cg.shared.global [%0], [%1], 16;" :: "r"(sdst), "l"(gsrc));
}
__device__ __forceinline__ void cp_commit() { asm volatile("cp.async.commit_group;"); }
template<int N> __device__ __forceinline__ void cp_wait() {
    asm volatile("cp.async.wait_group %0;" :: "n"(N));
}
__device__ __forceinline__ void ldsm4(uint32_t& r0, uint32_t& r1, uint32_t& r2, uint32_t& r3,
                                      uint32_t addr) {
    asm volatile("ldmatrix.sync.aligned.m8n8.x4.shared.b16 {%0,%1,%2,%3}, [%4];"
                 : "=r"(r0), "=r"(r1), "=r"(r2), "=r"(r3) : "r"(addr));
}
__device__ __forceinline__ void mma_fp16(float* c, const uint32_t* a, const uint32_t* b) {
    asm volatile(
        "mma.sync.aligned.m16n8k16.row.col.f32.f16.f16.f32 "
        "{%0,%1,%2,%3}, {%4,%5,%6,%7}, {%8,%9}, {%0,%1,%2,%3};"
        : "+f"(c[0]), "+f"(c[1]), "+f"(c[2]), "+f"(c[3])
        : "r"(a[0]), "r"(a[1]), "r"(a[2]), "r"(a[3]), "r"(b[0]), "r"(b[1]));
}

// ---------------- device scratch (zero-initialized at module load) ----------------
__device__ int   g_eidx[NSLOT];
__device__ float g_wt[NSLOT];
__device__ int   g_pos[NSLOT];
__device__ int   g_counts[NEXP];       // invariant: zero at every kernel_launch entry
__device__ int   g_perm[NEXP * ECAP];
__device__ int4  g_tiles[MAXTILES];
__device__ int   g_ntiles;
__device__ float g_slot_out[(size_t)NSLOT * DIMX];

__device__ __half g_xhi[NTOK * DIMX];
__device__ __half g_xlo[NTOK * DIMX];
__device__ __half g_w13h[(size_t)NEXP * 128 * DIMX];   // [e][n=128(j1|j3)][k=512] fp16
__device__ __half g_w2h[(size_t)NEXP * DIMX * INTER];  // [e][d=512][j=64] fp16

// ---------------- kernel A: fused prep + gate ----------------
// blocks [0,512): split x ; [512,1040): w13 cvt ; [1040,1568): w2 cvt ;
// blocks [1568,1600): gate (independent of prep work; overlaps its streaming)
__global__ __launch_bounds__(256) void prepgate_kernel(
    const float* __restrict__ x, const float* __restrict__ w1,
    const float* __restrict__ w3, const float* __restrict__ w2,
    const float* __restrict__ gw, const float* __restrict__ bias)
{
    int blk = blockIdx.x;
    int tid = threadIdx.x;

    if (blk < 512) {                        // ---- split x into fp16 hi/lo ----
        int i = (blk * 256 + tid) * 4;
        float4 v = *reinterpret_cast<const float4*>(x + i);
        __half h0 = __float2half_rn(v.x), h1 = __float2half_rn(v.y);
        __half h2 = __float2half_rn(v.z), h3 = __float2half_rn(v.w);
        __half l0 = __float2half_rn(v.x - __half2float(h0));
        __half l1 = __float2half_rn(v.y - __half2float(h1));
        __half l2 = __float2half_rn(v.z - __half2float(h2));
        __half l3 = __float2half_rn(v.w - __half2float(h3));
        *reinterpret_cast<__half2*>(g_xhi + i)     = __halves2half2(h0, h1);
        *reinterpret_cast<__half2*>(g_xhi + i + 2) = __halves2half2(h2, h3);
        *reinterpret_cast<__half2*>(g_xlo + i)     = __halves2half2(l0, l1);
        *reinterpret_cast<__half2*>(g_xlo + i + 2) = __halves2half2(l2, l3);
        return;
    }
    if (blk < 1040) {                       // ---- transpose + cvt W1||W3 ----
        int id = blk - 512;
        int e = id >> 3, kb = id & 7;
        __shared__ float T1[64][65], T3[64][65];
        #pragma unroll
        for (int q = 0; q < 16; q++) {
            int idx = tid + q * 256;
            int kk = idx >> 6, j = idx & 63;
            size_t s = ((size_t)e * DIMX + kb * 64 + kk) * INTER + j;
            T1[kk][j] = w1[s];
            T3[kk][j] = w3[s];
        }
        __syncthreads();
        #pragma unroll
        for (int q = 0; q < 16; q++) {
            int idx = tid + q * 256;
            int j = idx >> 6, kk = idx & 63;
            size_t o1 = ((size_t)e * 128 + j) * DIMX + kb * 64 + kk;
            size_t o3 = ((size_t)e * 128 + 64 + j) * DIMX + kb * 64 + kk;
            g_w13h[o1] = __float2half_rn(T1[kk][j]);
            g_w13h[o3] = __float2half_rn(T3[kk][j]);
        }
        return;
    }
    if (blk < 1568) {                       // ---- transpose + cvt W2 ----
        int id = blk - 1040;
        int e = id >> 3, db = id & 7;
        __shared__ float T[64][65];
        #pragma unroll
        for (int q = 0; q < 16; q++) {
            int idx = tid + q * 256;
            int j = idx >> 6, d = idx & 63;
            T[j][d] = w2[((size_t)e * INTER + j) * DIMX + db * 64 + d];
        }
        __syncthreads();
        #pragma unroll
        for (int q = 0; q < 16; q++) {
            int idx = tid + q * 256;
            int d = idx >> 6, j = idx & 63;
            size_t o = ((size_t)e * DIMX + db * 64 + d) * INTER + j;
            g_w2h[o] = __float2half_rn(T[j][d]);
        }
        return;
    }

    // ---------------- gate branch (blocks 1568..1599) ----------------
    {
        __shared__ float Xs[32][32];
        __shared__ float Gs[32][65];
        __shared__ float S[32][66];

        int tok0 = (blk - 1568) * 32;
        int tg   = tid >> 5;
        int lane = tid & 31;

        float acc[4][2] = {};

        for (int k0 = 0; k0 < DIMX; k0 += 32) {
            {
                int r = tid >> 3;
                int c = (tid & 7) * 4;
                float4 v = *reinterpret_cast<const float4*>(&x[(size_t)(tok0 + r) * DIMX + k0 + c]);
                Xs[r][c] = v.x; Xs[r][c+1] = v.y; Xs[r][c+2] = v.z; Xs[r][c+3] = v.w;
            }
            {
                int e  = tid >> 2;
                int kk = (tid & 3) * 8;
                float4 a = *reinterpret_cast<const float4*>(&gw[(size_t)e * DIMX + k0 + kk]);
                float4 b = *reinterpret_cast<const float4*>(&gw[(size_t)e * DIMX + k0 + kk + 4]);
                Gs[kk+0][e] = a.x; Gs[kk+1][e] = a.y; Gs[kk+2][e] = a.z; Gs[kk+3][e] = a.w;
                Gs[kk+4][e] = b.x; Gs[kk+5][e] = b.y; Gs[kk+6][e] = b.z; Gs[kk+7][e] = b.w;
            }
            __syncthreads();
            #pragma unroll
            for (int kk = 0; kk < 32; kk++) {
                float g0 = Gs[kk][lane], g1 = Gs[kk][lane + 32];
                #pragma unroll
                for (int i = 0; i < 4; i++) {
                    float xv = Xs[tg * 4 + i][kk];
                    acc[i][0] = fmaf(xv, g0, acc[i][0]);
                    acc[i][1] = fmaf(xv, g1, acc[i][1]);
                }
            }
            __syncthreads();
        }
        #pragma unroll
        for (int i = 0; i < 4; i++) {
            S[tg * 4 + i][lane]      = acc[i][0];
            S[tg * 4 + i][lane + 32] = acc[i][1];
        }
        __syncthreads();

        float b0 = bias[lane], b1 = bias[lane + 32];
        for (int i = 0; i < 4; i++) {
            int t = tg * 4 + i;
            float s0 = S[t][lane], s1 = S[t][lane + 32];
            float mx = fmaxf(s0, s1);
            #pragma unroll
            for (int o = 16; o > 0; o >>= 1) mx = fmaxf(mx, __shfl_xor_sync(0xffffffffu, mx, o));
            float e0 = expf(s0 - mx), e1 = expf(s1 - mx);
            float z = e0 + e1;
            #pragma unroll
            for (int o = 16; o > 0; o >>= 1) z += __shfl_xor_sync(0xffffffffu, z, o);
            float inv = 1.0f / z;
            float p0 = e0 * inv, p1 = e1 * inv;
            float k0v = p0 + b0, k1v = p1 + b1;
            int gt = tok0 + t;
            for (int r = 0; r < TOPK; r++) {
                float key, pv; int idx;
                if (k0v >= k1v) { key = k0v; pv = p0; idx = lane; }
                else            { key = k1v; pv = p1; idx = lane + 32; }
                #pragma unroll
                for (int o = 16; o > 0; o >>= 1) {
                    float ok = __shfl_xor_sync(0xffffffffu, key, o);
                    float op = __shfl_xor_sync(0xffffffffu, pv,  o);
                    int   oi = __shfl_xor_sync(0xffffffffu, idx, o);
                    if (ok > key || (ok == key && oi < idx)) { key = ok; pv = op; idx = oi; }
                }
                if (lane == 0) {
                    int slot = gt * KSLOT + NSH + r;
                    g_eidx[slot] = idx + NSH;
                    g_wt  [slot] = pv;
                    g_pos [slot] = atomicAdd(&g_counts[idx + NSH], 1);
                }
                if (idx == lane)           k0v = -INFINITY;
                else if (idx == lane + 32) k1v = -INFINITY;
            }
            if (lane < NSH) {
                int slot = gt * KSLOT + lane;
                g_eidx[slot] = lane;
                g_wt  [slot] = 1.0f;
                g_pos [slot] = gt;
            }
        }
    }
}

// ---------------- kernel B: fused scatter + parallel scan (+counts reset) ----------------
__global__ void scatscan_kernel() {
    if (blockIdx.x < 32) {
        int i = blockIdx.x * 256 + threadIdx.x;
        int e = g_eidx[i];
        g_perm[e * ECAP + g_pos[i]] = i;
    } else {
        __shared__ int cnt[NEXP];
        __shared__ int pre[NEXP + 1];
        int t = threadIdx.x;
        if (t < NEXP) cnt[t] = (t < NSH) ? NTOK : g_counts[t];
        __syncthreads();
        if (t == 0) {                      // tiny serial prefix over 66 smem ints
            int s = 0;
            for (int e = 0; e < NEXP; e++) {
                pre[e] = s;
                s += (cnt[e] + TILE_M - 1) / TILE_M;
            }
            g_ntiles = s;
        }
        __syncthreads();
        if (t < NEXP) {                    // parallel per-expert tile writes
            int base = pre[t], c = cnt[t];
            for (int j = 0, k = 0; j < c; j += TILE_M, k++)
                g_tiles[base + k] = make_int4(t, t * ECAP + j, min(TILE_M, c - j), 0);
            if (t >= NSH) g_counts[t] = 0; // restore zero-invariant for next replay
        }
    }
}

// ---------------- kernel 4: grouped expert FFN, fp16 2-pass mma.sync (proven) ----------------
__global__ void __launch_bounds__(256, 2) ffn_mma_kernel()
{
    extern __shared__ __align__(16) char dyn[];
    __shared__ int   toks[TILE_M];
    __shared__ float wts[TILE_M];
    __shared__ int   slots[TILE_M];

    int bid = blockIdx.x;
    if (bid >= g_ntiles) return;
    int4 tl = g_tiles[bid];
    int e = tl.x, p0 = tl.y, m = tl.z;

    int tid = threadIdx.x, wid = tid >> 5, lane = tid & 31;
    int mg = wid >> 2;          // token half 0/1
    int nw = wid & 3;           // N slice

    uint32_t sb = smem_u32(dyn);
    uint32_t Ah[2] = { sb,          sb + 4096  };
    uint32_t Al[2] = { sb + 8192,   sb + 12288 };
    uint32_t Bh[2] = { sb + 16384,  sb + 32768 };
    uint32_t Gh = sb + 49152, Gl = sb + 53248;

    if (tid < TILE_M) {
        int i = (tid < m) ? g_perm[p0 + tid] : g_perm[p0];
        slots[tid] = i; toks[tid] = i >> 3; wts[tid] = g_wt[i];
    }
    __syncthreads();

    const __half* w13 = g_w13h + (size_t)e * 128 * DIMX;
    const __half* w2e = g_w2h  + (size_t)e * DIMX * INTER;

    auto stage_A = [&](const __half* src, uint32_t dst, int kb) {
        int row = tid >> 3, c = tid & 7;
        cp16(dst + row * 128 + ((c ^ (row & 7)) << 4),
             src + (size_t)toks[row] * DIMX + kb * 64 + c * 8);
    };
    auto stage_B = [&](const __half* src, uint32_t dst, int kb) {
        #pragma unroll
        for (int q = 0; q < 4; q++) {
            int idx = tid + q * 256;
            int row = idx >> 3, c = idx & 7;
            cp16(dst + row * 128 + ((c ^ (row & 7)) << 4),
                 src + (size_t)row * DIMX + kb * 64 + c * 8);
        }
    };
    auto stage_W2 = [&](const __half* src, uint32_t dst, int chunk) {
        #pragma unroll
        for (int q = 0; q < 4; q++) {
            int idx = tid + q * 256;
            int row = idx >> 3, c = idx & 7;
            cp16(dst + row * 128 + ((c ^ (row & 7)) << 4),
                 src + (size_t)(chunk * 128 + row) * INTER + c * 8);
        }
    };

    auto addrA = [&](uint32_t base, int mt, int k0) {
        int row = mt * 16 + (lane & 15);
        int kc  = (k0 >> 3) + (lane >> 4);
        return base + row * 128 + (((uint32_t)kc ^ (row & 7)) << 4);
    };
    auto addrB = [&](uint32_t base, int nb, int k0) {
        int row = nb + (lane & 7) + ((lane >> 4) << 3);
        int kc  = (k0 >> 3) + ((lane >> 3) & 1);
        return base + row * 128 + (((uint32_t)kc ^ (row & 7)) << 4);
    };

    // ---- h-stage ----
    float acc[4][4] = {};

    stage_A(g_xhi, Ah[0], 0); stage_A(g_xlo, Al[0], 0);
    stage_B(w13, Bh[0], 0);
    cp_commit();

    #pragma unroll 1
    for (int kb = 0; kb < 8; kb++) {
        int b = kb & 1;
        if (kb + 1 < 8) {
            int nb = b ^ 1;
            stage_A(g_xhi, Ah[nb], kb + 1); stage_A(g_xlo, Al[nb], kb + 1);
            stage_B(w13, Bh[nb], kb + 1);
            cp_commit();
            cp_wait<1>();
        } else {
            cp_wait<0>();
        }
        __syncthreads();

        #pragma unroll
        for (int pass = 0; pass < 2; pass++) {
            uint32_t Abase = pass ? Al[b] : Ah[b];
            uint32_t Bbase = Bh[b];
            #pragma unroll
            for (int ks = 0; ks < 4; ks++) {
                int k0 = ks * 16;
                uint32_t a[4], bt[4][2];
                ldsm4(a[0], a[1], a[2], a[3], addrA(Abase, mg, k0));
                {
                    uint32_t r0, r1, r2, r3;
                    ldsm4(r0, r1, r2, r3, addrB(Bbase, nw * 16, k0));
                    bt[0][0] = r0; bt[0][1] = r1; bt[1][0] = r2; bt[1][1] = r3;
                    ldsm4(r0, r1, r2, r3, addrB(Bbase, 64 + nw * 16, k0));
                    bt[2][0] = r0; bt[2][1] = r1; bt[3][0] = r2; bt[3][1] = r3;
                }
                #pragma unroll
                for (int nt = 0; nt < 4; nt++)
                    mma_fp16(acc[nt], a, bt[nt]);
            }
        }
        __syncthreads();
    }

    // prefetch W2 chunk 0 while epilogue runs
    stage_W2(w2e, Bh[0], 0);
    cp_commit();

    // ---- epilogue: g = silu(h1)*h3 -> Gh/Gl fp16 swizzled ----
    {
        int rbase = lane >> 2, cbase = (lane & 3) * 2;
        #pragma unroll
        for (int p = 0; p < 2; p++) {
            const float* h1 = acc[p];
            const float* h3 = acc[p + 2];
            #pragma unroll
            for (int half = 0; half < 2; half++) {
                int row = mg * 16 + rbase + half * 8;
                float v0 = h1[half * 2], v1 = h1[half * 2 + 1];
                float g0 = v0 / (1.0f + __expf(-v0)) * h3[half * 2];
                float g1 = v1 / (1.0f + __expf(-v1)) * h3[half * 2 + 1];
                __half h0 = __float2half_rn(g0), h1h = __float2half_rn(g1);
                __half l0 = __float2half_rn(g0 - __half2float(h0));
                __half l1 = __float2half_rn(g1 - __half2float(h1h));
                int j = nw * 16 + p * 8 + cbase;
                uint32_t off = row * 128 + (((uint32_t)(j >> 3) ^ (row & 7)) << 4)
                               + (j & 7) * 2;
                *reinterpret_cast<__half2*>((char*)dyn + (Gh - sb) + off) = __halves2half2(h0, h1h);
                *reinterpret_cast<__half2*>((char*)dyn + (Gl - sb) + off) = __halves2half2(l0, l1);
            }
        }
    }
    __syncthreads();

    // ---- W2 stage: 4 chunks of 128 d, double-buffered, 2 passes ----
    int rbase = lane >> 2, cbase = (lane & 3) * 2;
    #pragma unroll 1
    for (int c = 0; c < 4; c++) {
        int b = c & 1;
        if (c + 1 < 4) {
            int nb = b ^ 1;
            stage_W2(w2e, Bh[nb], c + 1);
            cp_commit();
            cp_wait<1>();
        } else {
            cp_wait<0>();
        }
        __syncthreads();

        float oacc[4][4] = {};
        #pragma unroll
        for (int pass = 0; pass < 2; pass++) {
            uint32_t Abase = pass ? Gl : Gh;
            uint32_t Bbase = Bh[b];
            #pragma unroll
            for (int ks = 0; ks < 4; ks++) {
                int k0 = ks * 16;
                uint32_t a[4], bt[4][2];
                ldsm4(a[0], a[1], a[2], a[3], addrA(Abase, mg, k0));
                {
                    uint32_t r0, r1, r2, r3;
                    ldsm4(r0, r1, r2, r3, addrB(Bbase, nw * 32, k0));
                    bt[0][0] = r0; bt[0][1] = r1; bt[1][0] = r2; bt[1][1] = r3;
                    ldsm4(r0, r1, r2, r3, addrB(Bbase, nw * 32 + 16, k0));
                    bt[2][0] = r0; bt[2][1] = r1; bt[3][0] = r2; bt[3][1] = r3;
                }
                #pragma unroll
                for (int nt = 0; nt < 4; nt++)
                    mma_fp16(oacc[nt], a, bt[nt]);
            }
        }
        #pragma unroll
        for (int half = 0; half < 2; half++) {
            int r = mg * 16 + rbase + half * 8;
            if (r < m) {
                float wt = wts[r];
                float* orow = g_slot_out + (size_t)slots[r] * DIMX;
                #pragma unroll
                for (int nt = 0; nt < 4; nt++) {
                    int col = c * 128 + nw * 32 + nt * 8 + cbase;
                    float2 v;
                    v.x = oacc[nt][half * 2]     * wt;
                    v.y = oacc[nt][half * 2 + 1] * wt;
                    *reinterpret_cast<float2*>(orow + col) = v;
                }
            }
        }
        __syncthreads();
    }
}

// ---------------- kernel 5: combine ----------------
__global__ void combine_kernel(float* __restrict__ out) {
    int i = blockIdx.x * 256 + threadIdx.x;
    if (i >= NTOK * DIMX / 4) return;
    int t = i >> 7;
    int d4 = i & (DIMX/4 - 1);
    float4 s = make_float4(0.f, 0.f, 0.f, 0.f);
    #pragma unroll
    for (int sl = 0; sl < KSLOT; sl++) {
        const float4* p = reinterpret_cast<const float4*>(
            &g_slot_out[((size_t)(t * KSLOT + sl)) * DIMX]);
        float4 v = p[d4];
        s.x += v.x; s.y += v.y; s.z += v.z; s.w += v.w;
    }
    reinterpret_cast<float4*>(out)[i] = s;
}

// ---------------- launch ----------------
extern "C" void kernel_launch(void* const* d_in, const int* in_sizes, int n_in,
                              void* d_out, int out_size) {
    const float* x  = (const float*)d_in[0];
    const float* gw = (const float*)d_in[1];
    const float* gb = (const float*)d_in[2];
    const float* w1 = (const float*)d_in[3];
    const float* w2 = (const float*)d_in[4];
    const float* w3 = (const float*)d_in[5];
    float* out = (float*)d_out;

    const int ffn_smem = 57344;   // A 16K + B 32K + G 8K
    cudaFuncSetAttribute(ffn_mma_kernel,
                         cudaFuncAttributeMaxDynamicSharedMemorySize, ffn_smem);

    prepgate_kernel<<<1600, 256>>>(x, w1, w3, w2, gw, gb);
    scatscan_kernel<<<33, 256>>>();
    ffn_mma_kernel<<<MAXTILES, 256, ffn_smem>>>();
    combine_kernel<<<(NTOK * DIMX / 4) / 256, 256>>>(out);
}